// round 1
// baseline (speedup 1.0000x reference)
#include <cuda_runtime.h>
#include <cuda_bf16.h>
#include <math.h>

// ---------------- Problem constants ----------------
#define BATCH 4
#define SEQ   2048
#define EMB   1024
#define HEADS 16
#define DH    64
#define FF    4096
#define MTOK  (BATCH*SEQ)       // 8192

// ---------------- Scratch (alloc-free: __device__ globals) ----------------
__device__ __align__(256) float g_xn  [MTOK * EMB];      // LN1 output
__device__ __align__(256) float g_qkv [MTOK * 3 * EMB];  // QKV
__device__ __align__(256) float g_attn[MTOK * EMB];      // attention output (pre O-proj)
__device__ __align__(256) float g_x1  [MTOK * EMB];      // x + attn_proj (residual 1)
__device__ __align__(256) float g_h   [MTOK * EMB];      // LN2 output
__device__ __align__(256) float g_act [MTOK * FF];       // GELU(FC1)

// ---------------- LayerNorm: one block per row of 1024 ----------------
__global__ void __launch_bounds__(256) ln_kernel(const float* __restrict__ x,
                                                 const float* __restrict__ gam,
                                                 const float* __restrict__ bet,
                                                 float* __restrict__ out)
{
    int row = blockIdx.x;
    const float4* xr = (const float4*)(x + (size_t)row * EMB);
    float4 v = xr[threadIdx.x];
    float s  = v.x + v.y + v.z + v.w;
    float ss = v.x*v.x + v.y*v.y + v.z*v.z + v.w*v.w;
    #pragma unroll
    for (int o = 16; o; o >>= 1) {
        s  += __shfl_xor_sync(0xffffffffu, s,  o);
        ss += __shfl_xor_sync(0xffffffffu, ss, o);
    }
    __shared__ float sh[2][8];
    int w = threadIdx.x >> 5, l = threadIdx.x & 31;
    if (l == 0) { sh[0][w] = s; sh[1][w] = ss; }
    __syncthreads();
    if (threadIdx.x < 32) {
        float a  = (l < 8) ? sh[0][l] : 0.f;
        float bb = (l < 8) ? sh[1][l] : 0.f;
        #pragma unroll
        for (int o = 4; o; o >>= 1) {
            a  += __shfl_xor_sync(0xffffffffu, a,  o);
            bb += __shfl_xor_sync(0xffffffffu, bb, o);
        }
        if (l == 0) { sh[0][0] = a; sh[1][0] = bb; }
    }
    __syncthreads();
    float mean = sh[0][0] * (1.f / EMB);
    float var  = sh[1][0] * (1.f / EMB) - mean * mean;
    float inv  = rsqrtf(var + 1e-5f);
    int c = threadIdx.x * 4;
    float4 gg = *(const float4*)(gam + c);
    float4 bb4 = *(const float4*)(bet + c);
    float4 o4;
    o4.x = (v.x - mean) * inv * gg.x + bb4.x;
    o4.y = (v.y - mean) * inv * gg.y + bb4.y;
    o4.z = (v.z - mean) * inv * gg.z + bb4.z;
    o4.w = (v.w - mean) * inv * gg.w + bb4.w;
    ((float4*)(out + (size_t)row * EMB))[threadIdx.x] = o4;
}

// ---------------- GELU (exact, matches approximate=False) ----------------
__device__ __forceinline__ float geluf(float x) {
    return 0.5f * x * (1.f + erff(x * 0.70710678118654752f));
}

// ---------------- SGEMM: C[M,N] = A[M,K] @ Bw[N,K]^T + bias (+epilogue) ----
// MODE 0: +bias            MODE 1: +bias +res
// MODE 2: gelu(+bias)      MODE 3: +bias +res
template<int MODE>
__global__ void __launch_bounds__(256) sgemm_kernel(
    const float* __restrict__ A, const float* __restrict__ Bw,
    const float* __restrict__ bias, const float* __restrict__ res,
    float* __restrict__ C, int M, int N, int K)
{
    __shared__ float As[8][128];
    __shared__ float Bs[8][128];
    const int bm = blockIdx.y * 128, bn = blockIdx.x * 128;
    const int tid  = threadIdx.x;
    const int lrow = tid >> 1;              // 0..127
    const int lcol = (tid & 1) << 2;        // 0 or 4
    const int tx = tid & 15, ty = tid >> 4; // 16x16 compute grid

    const float* Aptr = A  + (size_t)(bm + lrow) * K + lcol;
    const float* Bptr = Bw + (size_t)(bn + lrow) * K + lcol;

    float acc[8][8];
    #pragma unroll
    for (int i = 0; i < 8; i++)
        #pragma unroll
        for (int j = 0; j < 8; j++) acc[i][j] = 0.f;

    for (int k0 = 0; k0 < K; k0 += 8) {
        float4 av = *(const float4*)(Aptr + k0);
        float4 bv = *(const float4*)(Bptr + k0);
        As[lcol+0][lrow] = av.x; As[lcol+1][lrow] = av.y;
        As[lcol+2][lrow] = av.z; As[lcol+3][lrow] = av.w;
        Bs[lcol+0][lrow] = bv.x; Bs[lcol+1][lrow] = bv.y;
        Bs[lcol+2][lrow] = bv.z; Bs[lcol+3][lrow] = bv.w;
        __syncthreads();
        #pragma unroll
        for (int kk = 0; kk < 8; kk++) {
            float4 a0 = *(const float4*)&As[kk][ty*8];
            float4 a1 = *(const float4*)&As[kk][ty*8+4];
            float4 b0 = *(const float4*)&Bs[kk][tx*8];
            float4 b1 = *(const float4*)&Bs[kk][tx*8+4];
            float ar[8] = {a0.x,a0.y,a0.z,a0.w,a1.x,a1.y,a1.z,a1.w};
            float br[8] = {b0.x,b0.y,b0.z,b0.w,b1.x,b1.y,b1.z,b1.w};
            #pragma unroll
            for (int i = 0; i < 8; i++)
                #pragma unroll
                for (int j = 0; j < 8; j++)
                    acc[i][j] += ar[i] * br[j];
        }
        __syncthreads();
    }

    #pragma unroll
    for (int i = 0; i < 8; i++) {
        int row = bm + ty*8 + i;
        #pragma unroll
        for (int j4 = 0; j4 < 2; j4++) {
            int col = bn + tx*8 + j4*4;
            float4 v;
            v.x = acc[i][j4*4+0] + bias[col+0];
            v.y = acc[i][j4*4+1] + bias[col+1];
            v.z = acc[i][j4*4+2] + bias[col+2];
            v.w = acc[i][j4*4+3] + bias[col+3];
            if (MODE == 1 || MODE == 3) {
                float4 r = *(const float4*)(res + (size_t)row * N + col);
                v.x += r.x; v.y += r.y; v.z += r.z; v.w += r.w;
            }
            if (MODE == 2) {
                v.x = geluf(v.x); v.y = geluf(v.y);
                v.z = geluf(v.z); v.w = geluf(v.w);
            }
            *(float4*)(C + (size_t)row * N + col) = v;
        }
    }
}

// ---------------- Attention: flash-style, 64x64 tiles ----------------
// grid = (S/64, H, B). 256 threads.
// mask: blocked if (j > i) or (j % td == td-1).
__global__ void __launch_bounds__(256) attn_kernel(
    const float* __restrict__ qkv, const int* __restrict__ tdp,
    float* __restrict__ out)
{
    extern __shared__ float sm[];
    float* Qs = sm;            // [64][64]
    float* Ks = sm + 4096;     // [64][64]
    float* Vs = sm + 8192;     // [64][64]
    float* Ss = sm + 12288;    // [64][64] scores -> P

    const int qt = blockIdx.x, h = blockIdx.y, b = blockIdx.z;
    const int tid = threadIdx.x;
    const int td = *tdp;

    // Load Q tile with 1/sqrt(Dh) folded in
    for (int i = tid; i < 1024; i += 256) {
        int r = i >> 4, c4 = i & 15;
        size_t off = ((size_t)(b*SEQ + qt*64 + r)) * (3*EMB) + h*DH + c4*4;
        float4 v = *(const float4*)(qkv + off);
        v.x *= 0.125f; v.y *= 0.125f; v.z *= 0.125f; v.w *= 0.125f;
        *(float4*)(Qs + r*64 + c4*4) = v;
    }

    const int ty = tid >> 4, tx = tid & 15;   // score compute: 4x4 per thread
    const int srow = tid >> 2, part = tid & 3; // softmax/PV: row + 16-col slice

    float O[16];
    #pragma unroll
    for (int d = 0; d < 16; d++) O[d] = 0.f;
    float mrun = -1e30f, lrun = 0.f;

    for (int kt = 0; kt <= qt; kt++) {
        __syncthreads();  // protect prior Ss/Vs reads before overwrite
        for (int i = tid; i < 1024; i += 256) {
            int r = i >> 4, c4 = i & 15;
            size_t tok = (size_t)(b*SEQ + kt*64 + r);
            *(float4*)(Ks + r*64 + c4*4) =
                *(const float4*)(qkv + tok*(3*EMB) + EMB   + h*DH + c4*4);
            *(float4*)(Vs + r*64 + c4*4) =
                *(const float4*)(qkv + tok*(3*EMB) + 2*EMB + h*DH + c4*4);
        }
        __syncthreads();

        // scores: 4x4 micro-tile, vectorized over d
        float acc[4][4];
        #pragma unroll
        for (int i = 0; i < 4; i++)
            #pragma unroll
            for (int j = 0; j < 4; j++) acc[i][j] = 0.f;
        #pragma unroll 4
        for (int d4 = 0; d4 < 16; d4++) {
            float4 qv[4], kv[4];
            #pragma unroll
            for (int i = 0; i < 4; i++)
                qv[i] = *(const float4*)(Qs + (ty*4+i)*64 + d4*4);
            #pragma unroll
            for (int j = 0; j < 4; j++)
                kv[j] = *(const float4*)(Ks + (tx*4+j)*64 + d4*4);
            #pragma unroll
            for (int i = 0; i < 4; i++)
                #pragma unroll
                for (int j = 0; j < 4; j++)
                    acc[i][j] += qv[i].x*kv[j].x + qv[i].y*kv[j].y
                               + qv[i].z*kv[j].z + qv[i].w*kv[j].w;
        }
        // mask + store to smem
        #pragma unroll
        for (int i = 0; i < 4; i++) {
            int gq = qt*64 + ty*4 + i;
            #pragma unroll
            for (int j = 0; j < 4; j++) {
                int gk = kt*64 + tx*4 + j;
                float s = acc[i][j];
                if (gk > gq || (gk % td) == td - 1) s = -1e30f;
                Ss[(ty*4+i)*64 + tx*4 + j] = s;
            }
        }
        __syncthreads();

        // online softmax on row srow, slice [part*16, part*16+16)
        float pv[16];
        float mloc = -1e30f;
        #pragma unroll
        for (int c = 0; c < 16; c++) {
            pv[c] = Ss[srow*64 + part*16 + c];
            mloc = fmaxf(mloc, pv[c]);
        }
        mloc = fmaxf(mloc, __shfl_xor_sync(0xffffffffu, mloc, 1));
        mloc = fmaxf(mloc, __shfl_xor_sync(0xffffffffu, mloc, 2));
        float mnew  = fmaxf(mrun, mloc);
        float alpha = __expf(mrun - mnew);
        float ps = 0.f;
        #pragma unroll
        for (int c = 0; c < 16; c++) {
            float p = __expf(pv[c] - mnew);
            ps += p;
            Ss[srow*64 + part*16 + c] = p;
        }
        ps += __shfl_xor_sync(0xffffffffu, ps, 1);
        ps += __shfl_xor_sync(0xffffffffu, ps, 2);
        lrun = lrun * alpha + ps;
        mrun = mnew;
        #pragma unroll
        for (int d = 0; d < 16; d++) O[d] *= alpha;
        __syncwarp();  // P for this row written by own group-of-4 (same warp)

        // O += P @ V  (this thread: row srow, dims part*16..+15)
        #pragma unroll 4
        for (int j = 0; j < 64; j++) {
            float p = Ss[srow*64 + j];
            const float4* vp = (const float4*)(Vs + j*64 + part*16);
            #pragma unroll
            for (int d4 = 0; d4 < 4; d4++) {
                float4 vv = vp[d4];
                O[d4*4+0] += p * vv.x; O[d4*4+1] += p * vv.y;
                O[d4*4+2] += p * vv.z; O[d4*4+3] += p * vv.w;
            }
        }
    }

    float inv = 1.f / lrun;
    size_t tok = (size_t)(b*SEQ + qt*64 + srow);
    float* op = out + tok*EMB + h*DH + part*16;
    #pragma unroll
    for (int d4 = 0; d4 < 4; d4++) {
        float4 v = make_float4(O[d4*4+0]*inv, O[d4*4+1]*inv,
                               O[d4*4+2]*inv, O[d4*4+3]*inv);
        *(float4*)(op + d4*4) = v;
    }
}

// ---------------- Launch ----------------
extern "C" void kernel_launch(void* const* d_in, const int* in_sizes, int n_in,
                              void* d_out, int out_size)
{
    const float* x     = (const float*)d_in[0];
    const int*   tdp   = (const int*)  d_in[1];
    const float* ln1_g = (const float*)d_in[2];
    const float* ln1_b = (const float*)d_in[3];
    const float* ln2_g = (const float*)d_in[4];
    const float* ln2_b = (const float*)d_in[5];
    const float* w_qkv = (const float*)d_in[6];
    const float* b_qkv = (const float*)d_in[7];
    const float* w_o   = (const float*)d_in[8];
    const float* b_o   = (const float*)d_in[9];
    const float* w_fc1 = (const float*)d_in[10];
    const float* b_fc1 = (const float*)d_in[11];
    const float* w_fc2 = (const float*)d_in[12];
    const float* b_fc2 = (const float*)d_in[13];
    float* out = (float*)d_out;

    float *xn, *qkvb, *attnb, *x1, *hb, *act;
    cudaGetSymbolAddress((void**)&xn,    g_xn);
    cudaGetSymbolAddress((void**)&qkvb,  g_qkv);
    cudaGetSymbolAddress((void**)&attnb, g_attn);
    cudaGetSymbolAddress((void**)&x1,    g_x1);
    cudaGetSymbolAddress((void**)&hb,    g_h);
    cudaGetSymbolAddress((void**)&act,   g_act);

    cudaFuncSetAttribute(attn_kernel,
        cudaFuncAttributeMaxDynamicSharedMemorySize, 64 * 1024);

    const int M = MTOK;

    // 1) LN1
    ln_kernel<<<M, 256>>>(x, ln1_g, ln1_b, xn);

    // 2) QKV = xn @ w_qkv^T + b_qkv      [8192, 3072]
    {
        dim3 grid(3*EMB/128, M/128);
        sgemm_kernel<0><<<grid, 256>>>(xn, w_qkv, b_qkv, nullptr, qkvb,
                                       M, 3*EMB, EMB);
    }

    // 3) attention -> g_attn
    {
        dim3 grid(SEQ/64, HEADS, BATCH);
        attn_kernel<<<grid, 256, 64*1024>>>(qkvb, tdp, attnb);
    }

    // 4) x1 = attn @ w_o^T + b_o + x
    {
        dim3 grid(EMB/128, M/128);
        sgemm_kernel<1><<<grid, 256>>>(attnb, w_o, b_o, x, x1,
                                       M, EMB, EMB);
    }

    // 5) LN2
    ln_kernel<<<M, 256>>>(x1, ln2_g, ln2_b, hb);

    // 6) act = gelu(h @ w_fc1^T + b_fc1)   [8192, 4096]
    {
        dim3 grid(FF/128, M/128);
        sgemm_kernel<2><<<grid, 256>>>(hb, w_fc1, b_fc1, nullptr, act,
                                       M, FF, EMB);
    }

    // 7) out = act @ w_fc2^T + b_fc2 + x1
    {
        dim3 grid(EMB/128, M/128);
        sgemm_kernel<3><<<grid, 256>>>(act, w_fc2, b_fc2, x1, out,
                                       M, EMB, FF);
    }
}

// round 4
// speedup vs baseline: 1.5722x; 1.5722x over previous
#include <cuda_runtime.h>
#include <cuda_bf16.h>
#include <math.h>
#include <stdint.h>

// ---------------- Problem constants ----------------
#define BATCH 4
#define SEQ   2048
#define EMB   1024
#define HEADS 16
#define DH    64
#define FF    4096
#define MTOK  (BATCH*SEQ)       // 8192

// ---------------- Scratch (alloc-free: __device__ globals) ----------------
__device__ __align__(256) float          g_qkv [MTOK * 3 * EMB];   // fp32 QKV
__device__ __align__(256) float          g_x1  [MTOK * EMB];       // residual 1 (fp32)
__device__ __align__(256) __nv_bfloat16  g_xn_h [MTOK * EMB];
__device__ __align__(256) __nv_bfloat16  g_xn_l [MTOK * EMB];
__device__ __align__(256) __nv_bfloat16  g_at_h [MTOK * EMB];
__device__ __align__(256) __nv_bfloat16  g_at_l [MTOK * EMB];
__device__ __align__(256) __nv_bfloat16  g_h_h  [MTOK * EMB];
__device__ __align__(256) __nv_bfloat16  g_h_l  [MTOK * EMB];
__device__ __align__(256) __nv_bfloat16  g_ac_h [MTOK * FF];
__device__ __align__(256) __nv_bfloat16  g_ac_l [MTOK * FF];
__device__ __align__(256) __nv_bfloat16  g_wqkv_h[3*EMB*EMB];
__device__ __align__(256) __nv_bfloat16  g_wqkv_l[3*EMB*EMB];
__device__ __align__(256) __nv_bfloat16  g_wo_h  [EMB*EMB];
__device__ __align__(256) __nv_bfloat16  g_wo_l  [EMB*EMB];
__device__ __align__(256) __nv_bfloat16  g_wf1_h [FF*EMB];
__device__ __align__(256) __nv_bfloat16  g_wf1_l [FF*EMB];
__device__ __align__(256) __nv_bfloat16  g_wf2_h [EMB*FF];
__device__ __align__(256) __nv_bfloat16  g_wf2_l [EMB*FF];

// ================= helpers =================
__device__ __forceinline__ uint32_t smem_u32(const void* p) {
    uint32_t a;
    asm("{ .reg .u64 t; cvta.to.shared.u64 t, %1; cvt.u32.u64 %0, t; }"
        : "=r"(a) : "l"(p));
    return a;
}
#define CP_ASYNC16(dst, src) \
    asm volatile("cp.async.cg.shared.global [%0], [%1], 16;" \
        :: "r"(dst), "l"(src) : "memory")
#define CP_COMMIT() asm volatile("cp.async.commit_group;" ::: "memory")
#define CP_WAIT1()  asm volatile("cp.async.wait_group 1;" ::: "memory")
#define CP_WAIT0()  asm volatile("cp.async.wait_group 0;" ::: "memory")

#define LDSM4(r0,r1,r2,r3, a) \
    asm volatile("ldmatrix.sync.aligned.m8n8.x4.shared.b16 {%0,%1,%2,%3}, [%4];" \
        : "=r"(r0),"=r"(r1),"=r"(r2),"=r"(r3) : "r"(a))

__device__ __forceinline__ void mma16816(float* d, const uint32_t* a, const uint32_t* b) {
    asm volatile(
        "mma.sync.aligned.m16n8k16.row.col.f32.bf16.bf16.f32 "
        "{%0,%1,%2,%3}, {%4,%5,%6,%7}, {%8,%9}, {%0,%1,%2,%3};"
        : "+f"(d[0]),"+f"(d[1]),"+f"(d[2]),"+f"(d[3])
        : "r"(a[0]),"r"(a[1]),"r"(a[2]),"r"(a[3]), "r"(b[0]),"r"(b[1]));
}

__device__ __forceinline__ float geluf(float x) {
    return 0.5f * x * (1.f + erff(x * 0.70710678118654752f));
}

__device__ __forceinline__ void splitbf(float v, __nv_bfloat16& h, __nv_bfloat16& l) {
    h = __float2bfloat16_rn(v);
    l = __float2bfloat16_rn(v - __bfloat162float(h));
}

// ============ bf16 hi/lo tensor-core GEMM ============
// C[M,N] = (Ah+Al)[M,K] @ (Bh+Bl)[N,K]^T + bias (+epilogue), 3-term split.
// MODE 0: fp32 +bias    1: fp32 +bias+res    2: gelu(+bias)->bf16 hi/lo   3: fp32 +bias+res
#define TG_SMEM 131072   // 2 stages x 4 tiles x 16KB

template<int MODE>
__global__ void __launch_bounds__(256, 1) tgemm(
    const __nv_bfloat16* __restrict__ Ah, const __nv_bfloat16* __restrict__ Al,
    const __nv_bfloat16* __restrict__ Bh, const __nv_bfloat16* __restrict__ Bl,
    const float* __restrict__ bias, const float* __restrict__ res,
    float* __restrict__ C, __nv_bfloat16* __restrict__ Ch, __nv_bfloat16* __restrict__ Cl,
    int M, int N, int K)
{
    extern __shared__ char smc[];
    const uint32_t smb = smem_u32(smc);
    const int tid = threadIdx.x;
    const int bm = blockIdx.y * 128, bn = blockIdx.x * 128;
    const int nck = K >> 6;
    const int lane = tid & 31, wid = tid >> 5;
    const int wm = wid & 1, wn = wid >> 1;

    float acc[4][4][4];
    #pragma unroll
    for (int i = 0; i < 4; i++)
        #pragma unroll
        for (int j = 0; j < 4; j++)
            #pragma unroll
            for (int e = 0; e < 4; e++) acc[i][j][e] = 0.f;

    const __nv_bfloat16* srcs[4] = {Ah, Al, Bh, Bl};
    const int rb0 = bm, rb2 = bn;

    auto issue = [&](int stage, int ck) {
        uint32_t sbase = smb + stage * 65536;
        #pragma unroll
        for (int t4 = 0; t4 < 4; t4++) {
            const __nv_bfloat16* s = srcs[t4];
            const int rbase = (t4 < 2) ? rb0 : rb2;
            #pragma unroll
            for (int p = 0; p < 4; p++) {
                int cid = tid + p * 256;
                int row = cid >> 3, c = cid & 7;
                const void* g = s + (size_t)(rbase + row) * K + ck * 64 + c * 8;
                uint32_t d = sbase + t4 * 16384 + row * 128 + ((c ^ (row & 7)) * 16);
                CP_ASYNC16(d, g);
            }
        }
        CP_COMMIT();
    };

    // lane addressing for ldmatrix
    const int arl = (lane & 7) + ((lane >> 3) & 1) * 8;  // A: row in m16
    const int acf = lane >> 4;                            // A: chunk offset (k8)
    const int brl = (lane & 7) + ((lane >> 4) & 1) * 8;  // B: row in n16
    const int bcf = (lane >> 3) & 1;                      // B: chunk offset

    auto domma = [&](int stage) {
        uint32_t Ab  = smb + stage * 65536;
        uint32_t Alb = Ab + 16384;
        uint32_t Bb  = Ab + 32768;
        uint32_t Blb = Ab + 49152;
        #pragma unroll
        for (int k16 = 0; k16 < 4; k16++) {
            uint32_t ah[4][4], al[4][4];
            #pragma unroll
            for (int mi = 0; mi < 4; mi++) {
                int r = wm * 64 + mi * 16 + arl;
                int c = k16 * 2 + acf;
                uint32_t off = r * 128 + ((c ^ (r & 7)) * 16);
                LDSM4(ah[mi][0], ah[mi][1], ah[mi][2], ah[mi][3], Ab  + off);
                LDSM4(al[mi][0], al[mi][1], al[mi][2], al[mi][3], Alb + off);
            }
            uint32_t bh[2][4], bl[2][4];
            #pragma unroll
            for (int np = 0; np < 2; np++) {
                int r = wn * 32 + np * 16 + brl;
                int c = k16 * 2 + bcf;
                uint32_t off = r * 128 + ((c ^ (r & 7)) * 16);
                LDSM4(bh[np][0], bh[np][1], bh[np][2], bh[np][3], Bb  + off);
                LDSM4(bl[np][0], bl[np][1], bl[np][2], bl[np][3], Blb + off);
            }
            #pragma unroll
            for (int mi = 0; mi < 4; mi++)
                #pragma unroll
                for (int ni = 0; ni < 4; ni++) {
                    const uint32_t* bph = &bh[ni >> 1][(ni & 1) * 2];
                    const uint32_t* bpl = &bl[ni >> 1][(ni & 1) * 2];
                    mma16816(acc[mi][ni], ah[mi], bph);
                    mma16816(acc[mi][ni], al[mi], bph);
                    mma16816(acc[mi][ni], ah[mi], bpl);
                }
        }
    };

    issue(0, 0);
    if (nck > 1) issue(1, 1);
    for (int ck = 0; ck < nck; ck++) {
        if (ck + 1 < nck) { CP_WAIT1(); } else { CP_WAIT0(); }
        __syncthreads();
        domma(ck & 1);
        __syncthreads();
        if (ck + 2 < nck) issue(ck & 1, ck + 2);
    }

    // ---------------- epilogue ----------------
    const int r_l = lane >> 2, c_l = (lane & 3) * 2;
    #pragma unroll
    for (int mi = 0; mi < 4; mi++) {
        #pragma unroll
        for (int ni = 0; ni < 4; ni++) {
            const int col = bn + wn * 32 + ni * 8 + c_l;
            const float2 bv = *(const float2*)(bias + col);
            #pragma unroll
            for (int h2 = 0; h2 < 2; h2++) {
                const int row = bm + wm * 64 + mi * 16 + r_l + h2 * 8;
                float v0 = acc[mi][ni][h2*2+0] + bv.x;
                float v1 = acc[mi][ni][h2*2+1] + bv.y;
                if (MODE == 1 || MODE == 3) {
                    float2 rr = *(const float2*)(res + (size_t)row * N + col);
                    v0 += rr.x; v1 += rr.y;
                }
                if (MODE == 2) {
                    v0 = geluf(v0); v1 = geluf(v1);
                    __nv_bfloat16 h0, l0, h1, l1;
                    splitbf(v0, h0, l0); splitbf(v1, h1, l1);
                    *(__nv_bfloat162*)(Ch + (size_t)row * N + col) = __halves2bfloat162(h0, h1);
                    *(__nv_bfloat162*)(Cl + (size_t)row * N + col) = __halves2bfloat162(l0, l1);
                } else {
                    *(float2*)(C + (size_t)row * N + col) = make_float2(v0, v1);
                }
            }
        }
    }
}

// ---------------- weight fp32 -> bf16 hi/lo ----------------
__global__ void __launch_bounds__(256) wconv_kernel(
    const float* __restrict__ s, __nv_bfloat16* __restrict__ h,
    __nv_bfloat16* __restrict__ l, int n)
{
    int i = (blockIdx.x * 256 + threadIdx.x) * 4;
    if (i >= n) return;
    float4 v = *(const float4*)(s + i);
    __nv_bfloat16 h0,l0,h1,l1,h2,l2,h3,l3;
    splitbf(v.x,h0,l0); splitbf(v.y,h1,l1); splitbf(v.z,h2,l2); splitbf(v.w,h3,l3);
    *(__nv_bfloat162*)(h + i)     = __halves2bfloat162(h0, h1);
    *(__nv_bfloat162*)(h + i + 2) = __halves2bfloat162(h2, h3);
    *(__nv_bfloat162*)(l + i)     = __halves2bfloat162(l0, l1);
    *(__nv_bfloat162*)(l + i + 2) = __halves2bfloat162(l2, l3);
}

// ---------------- LayerNorm -> bf16 hi/lo ----------------
__global__ void __launch_bounds__(256) ln_kernel(const float* __restrict__ x,
                                                 const float* __restrict__ gam,
                                                 const float* __restrict__ bet,
                                                 __nv_bfloat16* __restrict__ oh,
                                                 __nv_bfloat16* __restrict__ ol)
{
    int row = blockIdx.x;
    const float4* xr = (const float4*)(x + (size_t)row * EMB);
    float4 v = xr[threadIdx.x];
    float s  = v.x + v.y + v.z + v.w;
    float ss = v.x*v.x + v.y*v.y + v.z*v.z + v.w*v.w;
    #pragma unroll
    for (int o = 16; o; o >>= 1) {
        s  += __shfl_xor_sync(0xffffffffu, s,  o);
        ss += __shfl_xor_sync(0xffffffffu, ss, o);
    }
    __shared__ float sh[2][8];
    int w = threadIdx.x >> 5, l = threadIdx.x & 31;
    if (l == 0) { sh[0][w] = s; sh[1][w] = ss; }
    __syncthreads();
    if (threadIdx.x < 32) {
        float a  = (l < 8) ? sh[0][l] : 0.f;
        float bb = (l < 8) ? sh[1][l] : 0.f;
        #pragma unroll
        for (int o = 4; o; o >>= 1) {
            a  += __shfl_xor_sync(0xffffffffu, a,  o);
            bb += __shfl_xor_sync(0xffffffffu, bb, o);
        }
        if (l == 0) { sh[0][0] = a; sh[1][0] = bb; }
    }
    __syncthreads();
    float mean = sh[0][0] * (1.f / EMB);
    float var  = sh[1][0] * (1.f / EMB) - mean * mean;
    float inv  = rsqrtf(var + 1e-5f);
    int c = threadIdx.x * 4;
    float4 gg  = *(const float4*)(gam + c);
    float4 bb4 = *(const float4*)(bet + c);
    float o0 = (v.x - mean) * inv * gg.x + bb4.x;
    float o1 = (v.y - mean) * inv * gg.y + bb4.y;
    float o2 = (v.z - mean) * inv * gg.z + bb4.z;
    float o3 = (v.w - mean) * inv * gg.w + bb4.w;
    __nv_bfloat16 h0,l0,h1,l1,h2,l2,h3,l3;
    splitbf(o0,h0,l0); splitbf(o1,h1,l1); splitbf(o2,h2,l2); splitbf(o3,h3,l3);
    size_t base = (size_t)row * EMB + c;
    *(__nv_bfloat162*)(oh + base)     = __halves2bfloat162(h0, h1);
    *(__nv_bfloat162*)(oh + base + 2) = __halves2bfloat162(h2, h3);
    *(__nv_bfloat162*)(ol + base)     = __halves2bfloat162(l0, l1);
    *(__nv_bfloat162*)(ol + base + 2) = __halves2bfloat162(l2, l3);
}

// ---------------- Attention: flash-style, 64x64 tiles (fp32) ----------------
// outputs bf16 hi/lo for the O-projection GEMM
__global__ void __launch_bounds__(256) attn_kernel(
    const float* __restrict__ qkv, const int* __restrict__ tdp,
    __nv_bfloat16* __restrict__ oh, __nv_bfloat16* __restrict__ ol)
{
    extern __shared__ float smf[];
    float* Qs = smf;
    float* Ks = smf + 4096;
    float* Vs = smf + 8192;
    float* Ss = smf + 12288;

    const int qt = blockIdx.x, h = blockIdx.y, b = blockIdx.z;
    const int tid = threadIdx.x;
    const int td = *tdp;

    for (int i = tid; i < 1024; i += 256) {
        int r = i >> 4, c4 = i & 15;
        size_t off = ((size_t)(b*SEQ + qt*64 + r)) * (3*EMB) + h*DH + c4*4;
        float4 v = *(const float4*)(qkv + off);
        v.x *= 0.125f; v.y *= 0.125f; v.z *= 0.125f; v.w *= 0.125f;
        *(float4*)(Qs + r*64 + c4*4) = v;
    }

    const int ty = tid >> 4, tx = tid & 15;
    const int srow = tid >> 2, part = tid & 3;

    float O[16];
    #pragma unroll
    for (int d = 0; d < 16; d++) O[d] = 0.f;
    float mrun = -1e30f, lrun = 0.f;

    for (int kt = 0; kt <= qt; kt++) {
        __syncthreads();
        for (int i = tid; i < 1024; i += 256) {
            int r = i >> 4, c4 = i & 15;
            size_t tok = (size_t)(b*SEQ + kt*64 + r);
            *(float4*)(Ks + r*64 + c4*4) =
                *(const float4*)(qkv + tok*(3*EMB) + EMB   + h*DH + c4*4);
            *(float4*)(Vs + r*64 + c4*4) =
                *(const float4*)(qkv + tok*(3*EMB) + 2*EMB + h*DH + c4*4);
        }
        __syncthreads();

        float acc[4][4];
        #pragma unroll
        for (int i = 0; i < 4; i++)
            #pragma unroll
            for (int j = 0; j < 4; j++) acc[i][j] = 0.f;
        #pragma unroll 4
        for (int d4 = 0; d4 < 16; d4++) {
            float4 qv[4], kv[4];
            #pragma unroll
            for (int i = 0; i < 4; i++)
                qv[i] = *(const float4*)(Qs + (ty*4+i)*64 + d4*4);
            #pragma unroll
            for (int j = 0; j < 4; j++)
                kv[j] = *(const float4*)(Ks + (tx*4+j)*64 + d4*4);
            #pragma unroll
            for (int i = 0; i < 4; i++)
                #pragma unroll
                for (int j = 0; j < 4; j++)
                    acc[i][j] += qv[i].x*kv[j].x + qv[i].y*kv[j].y
                               + qv[i].z*kv[j].z + qv[i].w*kv[j].w;
        }
        #pragma unroll
        for (int i = 0; i < 4; i++) {
            int gq = qt*64 + ty*4 + i;
            #pragma unroll
            for (int j = 0; j < 4; j++) {
                int gk = kt*64 + tx*4 + j;
                float s = acc[i][j];
                if (gk > gq || (gk % td) == td - 1) s = -1e30f;
                Ss[(ty*4+i)*64 + tx*4 + j] = s;
            }
        }
        __syncthreads();

        float pv[16];
        float mloc = -1e30f;
        #pragma unroll
        for (int c = 0; c < 16; c++) {
            pv[c] = Ss[srow*64 + part*16 + c];
            mloc = fmaxf(mloc, pv[c]);
        }
        mloc = fmaxf(mloc, __shfl_xor_sync(0xffffffffu, mloc, 1));
        mloc = fmaxf(mloc, __shfl_xor_sync(0xffffffffu, mloc, 2));
        float mnew  = fmaxf(mrun, mloc);
        float alpha = __expf(mrun - mnew);
        float ps = 0.f;
        #pragma unroll
        for (int c = 0; c < 16; c++) {
            float p = __expf(pv[c] - mnew);
            ps += p;
            Ss[srow*64 + part*16 + c] = p;
        }
        ps += __shfl_xor_sync(0xffffffffu, ps, 1);
        ps += __shfl_xor_sync(0xffffffffu, ps, 2);
        lrun = lrun * alpha + ps;
        mrun = mnew;
        #pragma unroll
        for (int d = 0; d < 16; d++) O[d] *= alpha;
        __syncwarp();

        #pragma unroll 4
        for (int j = 0; j < 64; j++) {
            float p = Ss[srow*64 + j];
            const float4* vp = (const float4*)(Vs + j*64 + part*16);
            #pragma unroll
            for (int d4 = 0; d4 < 4; d4++) {
                float4 vv = vp[d4];
                O[d4*4+0] += p * vv.x; O[d4*4+1] += p * vv.y;
                O[d4*4+2] += p * vv.z; O[d4*4+3] += p * vv.w;
            }
        }
    }

    float inv = 1.f / lrun;
    size_t tok = (size_t)(b*SEQ + qt*64 + srow);
    size_t base = tok*EMB + h*DH + part*16;
    #pragma unroll
    for (int d2 = 0; d2 < 8; d2++) {
        float v0 = O[d2*2+0] * inv;
        float v1 = O[d2*2+1] * inv;
        __nv_bfloat16 h0,l0,h1,l1;
        splitbf(v0,h0,l0); splitbf(v1,h1,l1);
        *(__nv_bfloat162*)(oh + base + d2*2) = __halves2bfloat162(h0, h1);
        *(__nv_bfloat162*)(ol + base + d2*2) = __halves2bfloat162(l0, l1);
    }
}

// ---------------- Launch ----------------
extern "C" void kernel_launch(void* const* d_in, const int* in_sizes, int n_in,
                              void* d_out, int out_size)
{
    const float* x     = (const float*)d_in[0];
    const int*   tdp   = (const int*)  d_in[1];
    const float* ln1_g = (const float*)d_in[2];
    const float* ln1_b = (const float*)d_in[3];
    const float* ln2_g = (const float*)d_in[4];
    const float* ln2_b = (const float*)d_in[5];
    const float* w_qkv = (const float*)d_in[6];
    const float* b_qkv = (const float*)d_in[7];
    const float* w_o   = (const float*)d_in[8];
    const float* b_o   = (const float*)d_in[9];
    const float* w_fc1 = (const float*)d_in[10];
    const float* b_fc1 = (const float*)d_in[11];
    const float* w_fc2 = (const float*)d_in[12];
    const float* b_fc2 = (const float*)d_in[13];
    float* out = (float*)d_out;

    float *qkvb, *x1;
    __nv_bfloat16 *xnh, *xnl, *ath, *atl, *hh, *hl, *ach, *acl;
    __nv_bfloat16 *wqh, *wql, *woh, *wol, *w1h, *w1l, *w2h, *w2l;
    cudaGetSymbolAddress((void**)&qkvb, g_qkv);
    cudaGetSymbolAddress((void**)&x1,   g_x1);
    cudaGetSymbolAddress((void**)&xnh,  g_xn_h);  cudaGetSymbolAddress((void**)&xnl, g_xn_l);
    cudaGetSymbolAddress((void**)&ath,  g_at_h);  cudaGetSymbolAddress((void**)&atl, g_at_l);
    cudaGetSymbolAddress((void**)&hh,   g_h_h);   cudaGetSymbolAddress((void**)&hl,  g_h_l);
    cudaGetSymbolAddress((void**)&ach,  g_ac_h);  cudaGetSymbolAddress((void**)&acl, g_ac_l);
    cudaGetSymbolAddress((void**)&wqh,  g_wqkv_h); cudaGetSymbolAddress((void**)&wql, g_wqkv_l);
    cudaGetSymbolAddress((void**)&woh,  g_wo_h);   cudaGetSymbolAddress((void**)&wol, g_wo_l);
    cudaGetSymbolAddress((void**)&w1h,  g_wf1_h);  cudaGetSymbolAddress((void**)&w1l, g_wf1_l);
    cudaGetSymbolAddress((void**)&w2h,  g_wf2_h);  cudaGetSymbolAddress((void**)&w2l, g_wf2_l);

    cudaFuncSetAttribute(attn_kernel,
        cudaFuncAttributeMaxDynamicSharedMemorySize, 64 * 1024);
    cudaFuncSetAttribute(tgemm<0>, cudaFuncAttributeMaxDynamicSharedMemorySize, TG_SMEM);
    cudaFuncSetAttribute(tgemm<1>, cudaFuncAttributeMaxDynamicSharedMemorySize, TG_SMEM);
    cudaFuncSetAttribute(tgemm<2>, cudaFuncAttributeMaxDynamicSharedMemorySize, TG_SMEM);
    cudaFuncSetAttribute(tgemm<3>, cudaFuncAttributeMaxDynamicSharedMemorySize, TG_SMEM);

    const int M = MTOK;

    // weight conversions
    wconv_kernel<<<(3*EMB*EMB)/1024, 256>>>(w_qkv, wqh, wql, 3*EMB*EMB);
    wconv_kernel<<<(EMB*EMB)/1024,   256>>>(w_o,   woh, wol, EMB*EMB);
    wconv_kernel<<<(FF*EMB)/1024,    256>>>(w_fc1, w1h, w1l, FF*EMB);
    wconv_kernel<<<(EMB*FF)/1024,    256>>>(w_fc2, w2h, w2l, EMB*FF);

    // 1) LN1 -> bf16 hi/lo
    ln_kernel<<<M, 256>>>(x, ln1_g, ln1_b, xnh, xnl);

    // 2) QKV = xn @ w_qkv^T + b_qkv  -> fp32  [8192, 3072]
    {
        dim3 grid(3*EMB/128, M/128);
        tgemm<0><<<grid, 256, TG_SMEM>>>(xnh, xnl, wqh, wql, b_qkv, nullptr,
                                         qkvb, nullptr, nullptr, M, 3*EMB, EMB);
    }

    // 3) attention -> bf16 hi/lo
    {
        dim3 grid(SEQ/64, HEADS, BATCH);
        attn_kernel<<<grid, 256, 64*1024>>>(qkvb, tdp, ath, atl);
    }

    // 4) x1 = attn @ w_o^T + b_o + x   (fp32)
    {
        dim3 grid(EMB/128, M/128);
        tgemm<1><<<grid, 256, TG_SMEM>>>(ath, atl, woh, wol, b_o, x,
                                         x1, nullptr, nullptr, M, EMB, EMB);
    }

    // 5) LN2 -> bf16 hi/lo
    ln_kernel<<<M, 256>>>(x1, ln2_g, ln2_b, hh, hl);

    // 6) act = gelu(h @ w_fc1^T + b_fc1) -> bf16 hi/lo  [8192, 4096]
    {
        dim3 grid(FF/128, M/128);
        tgemm<2><<<grid, 256, TG_SMEM>>>(hh, hl, w1h, w1l, b_fc1, nullptr,
                                         nullptr, ach, acl, M, FF, EMB);
    }

    // 7) out = act @ w_fc2^T + b_fc2 + x1  (fp32)
    {
        dim3 grid(EMB/128, M/128);
        tgemm<3><<<grid, 256, TG_SMEM>>>(ach, acl, w2h, w2l, b_fc2, x1,
                                         out, nullptr, nullptr, M, EMB, FF);
    }
}

// round 5
// speedup vs baseline: 5.0084x; 3.1855x over previous
#include <cuda_runtime.h>
#include <cuda_bf16.h>
#include <math.h>
#include <stdint.h>

// ---------------- Problem constants ----------------
#define BATCH 4
#define SEQ   2048
#define EMB   1024
#define HEADS 16
#define DH    64
#define FF    4096
#define MTOK  (BATCH*SEQ)       // 8192

// ---------------- Scratch (alloc-free: __device__ globals) ----------------
__device__ __align__(256) float          g_x1  [MTOK * EMB];       // residual 1 (fp32)
__device__ __align__(256) __nv_bfloat16  g_xn_h [MTOK * EMB];
__device__ __align__(256) __nv_bfloat16  g_xn_l [MTOK * EMB];
__device__ __align__(256) __nv_bfloat16  g_q_h  [MTOK * EMB];      // head-major [B][H][S][DH]
__device__ __align__(256) __nv_bfloat16  g_q_l  [MTOK * EMB];
__device__ __align__(256) __nv_bfloat16  g_k_h  [MTOK * EMB];
__device__ __align__(256) __nv_bfloat16  g_k_l  [MTOK * EMB];
__device__ __align__(256) __nv_bfloat16  g_v_h  [MTOK * EMB];
__device__ __align__(256) __nv_bfloat16  g_v_l  [MTOK * EMB];
__device__ __align__(256) __nv_bfloat16  g_at_h [MTOK * EMB];
__device__ __align__(256) __nv_bfloat16  g_at_l [MTOK * EMB];
__device__ __align__(256) __nv_bfloat16  g_h_h  [MTOK * EMB];
__device__ __align__(256) __nv_bfloat16  g_h_l  [MTOK * EMB];
__device__ __align__(256) __nv_bfloat16  g_ac_h [MTOK * FF];
__device__ __align__(256) __nv_bfloat16  g_ac_l [MTOK * FF];
__device__ __align__(256) __nv_bfloat16  g_wqkv_h[3*EMB*EMB];
__device__ __align__(256) __nv_bfloat16  g_wqkv_l[3*EMB*EMB];
__device__ __align__(256) __nv_bfloat16  g_wo_h  [EMB*EMB];
__device__ __align__(256) __nv_bfloat16  g_wo_l  [EMB*EMB];
__device__ __align__(256) __nv_bfloat16  g_wf1_h [FF*EMB];
__device__ __align__(256) __nv_bfloat16  g_wf1_l [FF*EMB];
__device__ __align__(256) __nv_bfloat16  g_wf2_h [EMB*FF];
__device__ __align__(256) __nv_bfloat16  g_wf2_l [EMB*FF];

// ================= helpers =================
__device__ __forceinline__ uint32_t smem_u32(const void* p) {
    uint32_t a;
    asm("{ .reg .u64 t; cvta.to.shared.u64 t, %1; cvt.u32.u64 %0, t; }"
        : "=r"(a) : "l"(p));
    return a;
}
#define CP_ASYNC16(dst, src) \
    asm volatile("cp.async.cg.shared.global [%0], [%1], 16;" \
        :: "r"(dst), "l"(src) : "memory")
#define CP_COMMIT() asm volatile("cp.async.commit_group;" ::: "memory")
#define CP_WAIT1()  asm volatile("cp.async.wait_group 1;" ::: "memory")
#define CP_WAIT0()  asm volatile("cp.async.wait_group 0;" ::: "memory")

#define LDSM4(r0,r1,r2,r3, a) \
    asm volatile("ldmatrix.sync.aligned.m8n8.x4.shared.b16 {%0,%1,%2,%3}, [%4];" \
        : "=r"(r0),"=r"(r1),"=r"(r2),"=r"(r3) : "r"(a))
#define LDSM4T(r0,r1,r2,r3, a) \
    asm volatile("ldmatrix.sync.aligned.m8n8.x4.trans.shared.b16 {%0,%1,%2,%3}, [%4];" \
        : "=r"(r0),"=r"(r1),"=r"(r2),"=r"(r3) : "r"(a))

__device__ __forceinline__ void mma16816(float* d, const uint32_t* a, const uint32_t* b) {
    asm volatile(
        "mma.sync.aligned.m16n8k16.row.col.f32.bf16.bf16.f32 "
        "{%0,%1,%2,%3}, {%4,%5,%6,%7}, {%8,%9}, {%0,%1,%2,%3};"
        : "+f"(d[0]),"+f"(d[1]),"+f"(d[2]),"+f"(d[3])
        : "r"(a[0]),"r"(a[1]),"r"(a[2]),"r"(a[3]), "r"(b[0]),"r"(b[1]));
}

__device__ __forceinline__ float geluf(float x) {
    return 0.5f * x * (1.f + erff(x * 0.70710678118654752f));
}
__device__ __forceinline__ void splitbf(float v, __nv_bfloat16& h, __nv_bfloat16& l) {
    h = __float2bfloat16_rn(v);
    l = __float2bfloat16_rn(v - __bfloat162float(h));
}
__device__ __forceinline__ uint32_t pack_hi2(float a, float b) {
    __nv_bfloat162 t = __halves2bfloat162(__float2bfloat16_rn(a), __float2bfloat16_rn(b));
    return *(uint32_t*)&t;
}
__device__ __forceinline__ uint32_t pack_lo2(float a, float b) {
    __nv_bfloat16 ha = __float2bfloat16_rn(a), hb = __float2bfloat16_rn(b);
    __nv_bfloat162 t = __halves2bfloat162(
        __float2bfloat16_rn(a - __bfloat162float(ha)),
        __float2bfloat16_rn(b - __bfloat162float(hb)));
    return *(uint32_t*)&t;
}

// ============ bf16 hi/lo tensor-core GEMM ============
// MODE 0: unused  1: fp32 +bias+res  2: gelu(+bias)->bf16 hi/lo  3: fp32 +bias+res
// MODE 4: QKV epilogue -> head-major q/k/v hi/lo (q scaled by 0.125)
#define TG_SMEM 131072   // 2 stages x 4 tiles x 16KB

template<int MODE>
__global__ void __launch_bounds__(256, 1) tgemm(
    const __nv_bfloat16* __restrict__ Ah, const __nv_bfloat16* __restrict__ Al,
    const __nv_bfloat16* __restrict__ Bh, const __nv_bfloat16* __restrict__ Bl,
    const float* __restrict__ bias, const float* __restrict__ res,
    float* __restrict__ C, __nv_bfloat16* __restrict__ Ch, __nv_bfloat16* __restrict__ Cl,
    __nv_bfloat16* __restrict__ Qh, __nv_bfloat16* __restrict__ Ql,
    __nv_bfloat16* __restrict__ Kh, __nv_bfloat16* __restrict__ Kl,
    __nv_bfloat16* __restrict__ Vh, __nv_bfloat16* __restrict__ Vl,
    int M, int N, int K)
{
    extern __shared__ char smc[];
    const uint32_t smb = smem_u32(smc);
    const int tid = threadIdx.x;
    const int bm = blockIdx.y * 128, bn = blockIdx.x * 128;
    const int nck = K >> 6;
    const int lane = tid & 31, wid = tid >> 5;
    const int wm = wid & 1, wn = wid >> 1;

    float acc[4][4][4];
    #pragma unroll
    for (int i = 0; i < 4; i++)
        #pragma unroll
        for (int j = 0; j < 4; j++)
            #pragma unroll
            for (int e = 0; e < 4; e++) acc[i][j][e] = 0.f;

    const __nv_bfloat16* srcs[4] = {Ah, Al, Bh, Bl};

    auto issue = [&](int stage, int ck) {
        uint32_t sbase = smb + stage * 65536;
        #pragma unroll
        for (int t4 = 0; t4 < 4; t4++) {
            const __nv_bfloat16* s = srcs[t4];
            const int rbase = (t4 < 2) ? bm : bn;
            #pragma unroll
            for (int p = 0; p < 4; p++) {
                int cid = tid + p * 256;
                int row = cid >> 3, c = cid & 7;
                const void* g = s + (size_t)(rbase + row) * K + ck * 64 + c * 8;
                uint32_t d = sbase + t4 * 16384 + row * 128 + ((c ^ (row & 7)) * 16);
                CP_ASYNC16(d, g);
            }
        }
        CP_COMMIT();
    };

    const int arl = (lane & 7) + ((lane >> 3) & 1) * 8;
    const int acf = lane >> 4;
    const int brl = (lane & 7) + ((lane >> 4) & 1) * 8;
    const int bcf = (lane >> 3) & 1;

    auto domma = [&](int stage) {
        uint32_t Ab  = smb + stage * 65536;
        uint32_t Alb = Ab + 16384;
        uint32_t Bb  = Ab + 32768;
        uint32_t Blb = Ab + 49152;
        #pragma unroll
        for (int k16 = 0; k16 < 4; k16++) {
            uint32_t ah[4][4], al[4][4];
            #pragma unroll
            for (int mi = 0; mi < 4; mi++) {
                int r = wm * 64 + mi * 16 + arl;
                int c = k16 * 2 + acf;
                uint32_t off = r * 128 + ((c ^ (r & 7)) * 16);
                LDSM4(ah[mi][0], ah[mi][1], ah[mi][2], ah[mi][3], Ab  + off);
                LDSM4(al[mi][0], al[mi][1], al[mi][2], al[mi][3], Alb + off);
            }
            uint32_t bh[2][4], bl[2][4];
            #pragma unroll
            for (int np = 0; np < 2; np++) {
                int r = wn * 32 + np * 16 + brl;
                int c = k16 * 2 + bcf;
                uint32_t off = r * 128 + ((c ^ (r & 7)) * 16);
                LDSM4(bh[np][0], bh[np][1], bh[np][2], bh[np][3], Bb  + off);
                LDSM4(bl[np][0], bl[np][1], bl[np][2], bl[np][3], Blb + off);
            }
            #pragma unroll
            for (int mi = 0; mi < 4; mi++)
                #pragma unroll
                for (int ni = 0; ni < 4; ni++) {
                    const uint32_t* bph = &bh[ni >> 1][(ni & 1) * 2];
                    const uint32_t* bpl = &bl[ni >> 1][(ni & 1) * 2];
                    mma16816(acc[mi][ni], ah[mi], bph);
                    mma16816(acc[mi][ni], al[mi], bph);
                    mma16816(acc[mi][ni], ah[mi], bpl);
                }
        }
    };

    issue(0, 0);
    if (nck > 1) issue(1, 1);
    for (int ck = 0; ck < nck; ck++) {
        if (ck + 1 < nck) { CP_WAIT1(); } else { CP_WAIT0(); }
        __syncthreads();
        domma(ck & 1);
        __syncthreads();
        if (ck + 2 < nck) issue(ck & 1, ck + 2);
    }

    // ---------------- epilogue ----------------
    const int r_l = lane >> 2, c_l = (lane & 3) * 2;
    #pragma unroll
    for (int mi = 0; mi < 4; mi++) {
        #pragma unroll
        for (int ni = 0; ni < 4; ni++) {
            const int col = bn + wn * 32 + ni * 8 + c_l;
            const float2 bv = *(const float2*)(bias + col);
            #pragma unroll
            for (int h2 = 0; h2 < 2; h2++) {
                const int row = bm + wm * 64 + mi * 16 + r_l + h2 * 8;
                float v0 = acc[mi][ni][h2*2+0] + bv.x;
                float v1 = acc[mi][ni][h2*2+1] + bv.y;
                if (MODE == 1 || MODE == 3) {
                    float2 rr = *(const float2*)(res + (size_t)row * N + col);
                    v0 += rr.x; v1 += rr.y;
                    *(float2*)(C + (size_t)row * N + col) = make_float2(v0, v1);
                } else if (MODE == 2) {
                    v0 = geluf(v0); v1 = geluf(v1);
                    __nv_bfloat16 h0, l0, h1, l1;
                    splitbf(v0, h0, l0); splitbf(v1, h1, l1);
                    *(__nv_bfloat162*)(Ch + (size_t)row * N + col) = __halves2bfloat162(h0, h1);
                    *(__nv_bfloat162*)(Cl + (size_t)row * N + col) = __halves2bfloat162(l0, l1);
                } else if (MODE == 4) {
                    int sec = col >> 10;
                    int hd  = (col & 1023) >> 6;
                    int dch = col & 63;
                    int bb = row >> 11, s = row & 2047;
                    size_t di = (((size_t)bb * HEADS + hd) * SEQ + s) * DH + dch;
                    float sc = (sec == 0) ? 0.125f : 1.f;
                    v0 *= sc; v1 *= sc;
                    __nv_bfloat16 h0, l0, h1, l1;
                    splitbf(v0, h0, l0); splitbf(v1, h1, l1);
                    __nv_bfloat16* dsth = (sec == 0) ? Qh : (sec == 1) ? Kh : Vh;
                    __nv_bfloat16* dstl = (sec == 0) ? Ql : (sec == 1) ? Kl : Vl;
                    *(__nv_bfloat162*)(dsth + di) = __halves2bfloat162(h0, h1);
                    *(__nv_bfloat162*)(dstl + di) = __halves2bfloat162(l0, l1);
                } else {
                    *(float2*)(C + (size_t)row * N + col) = make_float2(v0, v1);
                }
            }
        }
    }
}

// ---------------- weight fp32 -> bf16 hi/lo ----------------
__global__ void __launch_bounds__(256) wconv_kernel(
    const float* __restrict__ s, __nv_bfloat16* __restrict__ h,
    __nv_bfloat16* __restrict__ l, int n)
{
    int i = (blockIdx.x * 256 + threadIdx.x) * 4;
    if (i >= n) return;
    float4 v = *(const float4*)(s + i);
    __nv_bfloat16 h0,l0,h1,l1,h2,l2,h3,l3;
    splitbf(v.x,h0,l0); splitbf(v.y,h1,l1); splitbf(v.z,h2,l2); splitbf(v.w,h3,l3);
    *(__nv_bfloat162*)(h + i)     = __halves2bfloat162(h0, h1);
    *(__nv_bfloat162*)(h + i + 2) = __halves2bfloat162(h2, h3);
    *(__nv_bfloat162*)(l + i)     = __halves2bfloat162(l0, l1);
    *(__nv_bfloat162*)(l + i + 2) = __halves2bfloat162(l2, l3);
}

// ---------------- LayerNorm -> bf16 hi/lo ----------------
__global__ void __launch_bounds__(256) ln_kernel(const float* __restrict__ x,
                                                 const float* __restrict__ gam,
                                                 const float* __restrict__ bet,
                                                 __nv_bfloat16* __restrict__ oh,
                                                 __nv_bfloat16* __restrict__ ol)
{
    int row = blockIdx.x;
    const float4* xr = (const float4*)(x + (size_t)row * EMB);
    float4 v = xr[threadIdx.x];
    float s  = v.x + v.y + v.z + v.w;
    float ss = v.x*v.x + v.y*v.y + v.z*v.z + v.w*v.w;
    #pragma unroll
    for (int o = 16; o; o >>= 1) {
        s  += __shfl_xor_sync(0xffffffffu, s,  o);
        ss += __shfl_xor_sync(0xffffffffu, ss, o);
    }
    __shared__ float sh[2][8];
    int w = threadIdx.x >> 5, l = threadIdx.x & 31;
    if (l == 0) { sh[0][w] = s; sh[1][w] = ss; }
    __syncthreads();
    if (threadIdx.x < 32) {
        float a  = (l < 8) ? sh[0][l] : 0.f;
        float bb = (l < 8) ? sh[1][l] : 0.f;
        #pragma unroll
        for (int o = 4; o; o >>= 1) {
            a  += __shfl_xor_sync(0xffffffffu, a,  o);
            bb += __shfl_xor_sync(0xffffffffu, bb, o);
        }
        if (l == 0) { sh[0][0] = a; sh[1][0] = bb; }
    }
    __syncthreads();
    float mean = sh[0][0] * (1.f / EMB);
    float var  = sh[1][0] * (1.f / EMB) - mean * mean;
    float inv  = rsqrtf(var + 1e-5f);
    int c = threadIdx.x * 4;
    float4 gg  = *(const float4*)(gam + c);
    float4 bb4 = *(const float4*)(bet + c);
    float o0 = (v.x - mean) * inv * gg.x + bb4.x;
    float o1 = (v.y - mean) * inv * gg.y + bb4.y;
    float o2 = (v.z - mean) * inv * gg.z + bb4.z;
    float o3 = (v.w - mean) * inv * gg.w + bb4.w;
    __nv_bfloat16 h0,l0,h1,l1,h2,l2,h3,l3;
    splitbf(o0,h0,l0); splitbf(o1,h1,l1); splitbf(o2,h2,l2); splitbf(o3,h3,l3);
    size_t base = (size_t)row * EMB + c;
    *(__nv_bfloat162*)(oh + base)     = __halves2bfloat162(h0, h1);
    *(__nv_bfloat162*)(oh + base + 2) = __halves2bfloat162(h2, h3);
    *(__nv_bfloat162*)(ol + base)     = __halves2bfloat162(l0, l1);
    *(__nv_bfloat162*)(ol + base + 2) = __halves2bfloat162(l2, l3);
}

// ---------------- Tensor-core flash attention ----------------
// 4 warps, 64x64 tile. hi/lo 3-term for both QK^T and PV.
// Q scaled by 0.125 already.  mask: (gk % td == td-1) || (kt==qt && gk > gq)
#define ATT_SMEM (16384 + 2*32768)   // Q hi/lo + 2 stages {Kh,Kl,Vh,Vl}

__global__ void __launch_bounds__(128, 1) attn_tc(
    const __nv_bfloat16* __restrict__ qh, const __nv_bfloat16* __restrict__ ql,
    const __nv_bfloat16* __restrict__ kh, const __nv_bfloat16* __restrict__ kl,
    const __nv_bfloat16* __restrict__ vh, const __nv_bfloat16* __restrict__ vl,
    const int* __restrict__ tdp,
    __nv_bfloat16* __restrict__ oh, __nv_bfloat16* __restrict__ ol)
{
    extern __shared__ char smc[];
    const uint32_t smb = smem_u32(smc);
    const int qt = (SEQ/64 - 1) - blockIdx.x;   // longest first
    const int h = blockIdx.y, b = blockIdx.z;
    const int tid = threadIdx.x, lane = tid & 31, wid = tid >> 5;
    const int td = *tdp;

    const size_t hb = ((size_t)b * HEADS + h) * SEQ * DH;
    const __nv_bfloat16* srcs[4] = {kh + hb, kl + hb, vh + hb, vl + hb};
    const int nkt = qt + 1;

    auto issue = [&](int stage, int kt) {
        uint32_t sb = smb + 16384 + stage * 32768;
        #pragma unroll
        for (int t4 = 0; t4 < 4; t4++) {
            #pragma unroll
            for (int p = 0; p < 4; p++) {
                int cid = tid + p * 128;
                int row = cid >> 3, c = cid & 7;
                const void* g = srcs[t4] + (size_t)(kt * 64 + row) * DH + c * 8;
                uint32_t d = sb + t4 * 8192 + row * 128 + ((c ^ (row & 7)) * 16);
                CP_ASYNC16(d, g);
            }
        }
        CP_COMMIT();
    };

    issue(0, 0);
    if (nkt > 1) issue(1, 1);

    // Q tile -> smem (hi/lo)
    {
        const __nv_bfloat16* qhp = qh + hb;
        const __nv_bfloat16* qlp = ql + hb;
        #pragma unroll
        for (int p = 0; p < 4; p++) {
            int cid = tid + p * 128;
            int row = cid >> 3, c = cid & 7;
            uint32_t sw = row * 128 + ((c ^ (row & 7)) * 16);
            size_t g = (size_t)(qt * 64 + row) * DH + c * 8;
            *(uint4*)(smc + sw)        = *(const uint4*)(qhp + g);
            *(uint4*)(smc + 8192 + sw) = *(const uint4*)(qlp + g);
        }
    }
    __syncthreads();

    // Q fragments (A operand), held in registers
    const int arl = (lane & 7) + ((lane >> 3) & 1) * 8;
    const int acf = lane >> 4;
    uint32_t qfh[4][4], qfl[4][4];
    #pragma unroll
    for (int j = 0; j < 4; j++) {
        int r = wid * 16 + arl;
        int c = j * 2 + acf;
        uint32_t off = r * 128 + ((c ^ (r & 7)) * 16);
        LDSM4(qfh[j][0], qfh[j][1], qfh[j][2], qfh[j][3], smb + off);
        LDSM4(qfl[j][0], qfl[j][1], qfl[j][2], qfl[j][3], smb + 8192 + off);
    }

    const int r_l = lane >> 2, c_l = lane & 3;
    const int brl = (lane & 7) + ((lane >> 4) & 1) * 8;
    const int bcf = (lane >> 3) & 1;
    const int vr  = (lane & 7) + ((lane >> 3) & 1) * 8;
    const int vc  = lane >> 4;

    float O[8][4] = {};
    float mrun[2] = {-1e30f, -1e30f}, lrun[2] = {0.f, 0.f};
    const int grow = qt * 64 + wid * 16 + r_l;

    for (int kt = 0; kt < nkt; kt++) {
        if (kt + 1 < nkt) { CP_WAIT1(); } else { CP_WAIT0(); }
        __syncthreads();
        uint32_t sb  = smb + 16384 + (kt & 1) * 32768;
        uint32_t KHb = sb, KLb = sb + 8192, VHb = sb + 16384, VLb = sb + 24576;

        // ---- scores S = Q K^T ----
        float sacc[8][4];
        #pragma unroll
        for (int t = 0; t < 8; t++)
            #pragma unroll
            for (int e = 0; e < 4; e++) sacc[t][e] = 0.f;

        #pragma unroll
        for (int j = 0; j < 4; j++) {
            uint32_t bhf[4][4], blf[4][4];
            #pragma unroll
            for (int np = 0; np < 4; np++) {
                int r = np * 16 + brl;
                int c = j * 2 + bcf;
                uint32_t off = r * 128 + ((c ^ (r & 7)) * 16);
                LDSM4(bhf[np][0], bhf[np][1], bhf[np][2], bhf[np][3], KHb + off);
                LDSM4(blf[np][0], blf[np][1], blf[np][2], blf[np][3], KLb + off);
            }
            #pragma unroll
            for (int np = 0; np < 4; np++) {
                mma16816(sacc[2*np],   qfh[j], &bhf[np][0]);
                mma16816(sacc[2*np],   qfl[j], &bhf[np][0]);
                mma16816(sacc[2*np],   qfh[j], &blf[np][0]);
                mma16816(sacc[2*np+1], qfh[j], &bhf[np][2]);
                mma16816(sacc[2*np+1], qfl[j], &bhf[np][2]);
                mma16816(sacc[2*np+1], qfh[j], &blf[np][2]);
            }
        }

        // ---- mask ----
        #pragma unroll
        for (int t = 0; t < 8; t++) {
            #pragma unroll
            for (int e = 0; e < 4; e++) {
                int gk = kt * 64 + t * 8 + c_l * 2 + (e & 1);
                int gq = grow + (e >> 1) * 8;
                if ((gk % td) == td - 1 || (kt == qt && gk > gq))
                    sacc[t][e] = -1e30f;
            }
        }

        // ---- online softmax (per row-half) ----
        #pragma unroll
        for (int rh = 0; rh < 2; rh++) {
            float mx = -1e30f;
            #pragma unroll
            for (int t = 0; t < 8; t++) {
                mx = fmaxf(mx, sacc[t][rh*2]);
                mx = fmaxf(mx, sacc[t][rh*2+1]);
            }
            mx = fmaxf(mx, __shfl_xor_sync(0xffffffffu, mx, 1));
            mx = fmaxf(mx, __shfl_xor_sync(0xffffffffu, mx, 2));
            float mnew  = fmaxf(mrun[rh], mx);
            float alpha = __expf(mrun[rh] - mnew);
            float sum = 0.f;
            #pragma unroll
            for (int t = 0; t < 8; t++) {
                float p0 = __expf(sacc[t][rh*2]   - mnew);
                float p1 = __expf(sacc[t][rh*2+1] - mnew);
                sacc[t][rh*2] = p0; sacc[t][rh*2+1] = p1;
                sum += p0 + p1;
            }
            sum += __shfl_xor_sync(0xffffffffu, sum, 1);
            sum += __shfl_xor_sync(0xffffffffu, sum, 2);
            lrun[rh] = lrun[rh] * alpha + sum;
            mrun[rh] = mnew;
            #pragma unroll
            for (int d = 0; d < 8; d++) {
                O[d][rh*2]   *= alpha;
                O[d][rh*2+1] *= alpha;
            }
        }

        // ---- O += P V ----
        #pragma unroll
        for (int j = 0; j < 4; j++) {
            uint32_t pah[4], pal[4];
            pah[0] = pack_hi2(sacc[2*j][0],   sacc[2*j][1]);
            pah[1] = pack_hi2(sacc[2*j][2],   sacc[2*j][3]);
            pah[2] = pack_hi2(sacc[2*j+1][0], sacc[2*j+1][1]);
            pah[3] = pack_hi2(sacc[2*j+1][2], sacc[2*j+1][3]);
            pal[0] = pack_lo2(sacc[2*j][0],   sacc[2*j][1]);
            pal[1] = pack_lo2(sacc[2*j][2],   sacc[2*j][3]);
            pal[2] = pack_lo2(sacc[2*j+1][0], sacc[2*j+1][1]);
            pal[3] = pack_lo2(sacc[2*j+1][2], sacc[2*j+1][3]);
            #pragma unroll
            for (int dp = 0; dp < 4; dp++) {
                uint32_t bvh[4], bvl[4];
                int r = j * 16 + vr;
                int c = dp * 2 + vc;
                uint32_t off = r * 128 + ((c ^ (r & 7)) * 16);
                LDSM4T(bvh[0], bvh[1], bvh[2], bvh[3], VHb + off);
                LDSM4T(bvl[0], bvl[1], bvl[2], bvl[3], VLb + off);
                mma16816(O[2*dp],   pah, &bvh[0]);
                mma16816(O[2*dp],   pal, &bvh[0]);
                mma16816(O[2*dp],   pah, &bvl[0]);
                mma16816(O[2*dp+1], pah, &bvh[2]);
                mma16816(O[2*dp+1], pal, &bvh[2]);
                mma16816(O[2*dp+1], pah, &bvl[2]);
            }
        }

        __syncthreads();
        if (kt + 2 < nkt) issue(kt & 1, kt + 2);
    }

    // ---- write O (token-major hi/lo) ----
    #pragma unroll
    for (int rh = 0; rh < 2; rh++) {
        float inv = 1.f / lrun[rh];
        int tok = b * SEQ + qt * 64 + wid * 16 + r_l + rh * 8;
        size_t base = (size_t)tok * EMB + h * DH + c_l * 2;
        #pragma unroll
        for (int t = 0; t < 8; t++) {
            float v0 = O[t][rh*2]   * inv;
            float v1 = O[t][rh*2+1] * inv;
            __nv_bfloat16 h0, l0, h1, l1;
            splitbf(v0, h0, l0); splitbf(v1, h1, l1);
            *(__nv_bfloat162*)(oh + base + t*8) = __halves2bfloat162(h0, h1);
            *(__nv_bfloat162*)(ol + base + t*8) = __halves2bfloat162(l0, l1);
        }
    }
}

// ---------------- Launch ----------------
extern "C" void kernel_launch(void* const* d_in, const int* in_sizes, int n_in,
                              void* d_out, int out_size)
{
    const float* x     = (const float*)d_in[0];
    const int*   tdp   = (const int*)  d_in[1];
    const float* ln1_g = (const float*)d_in[2];
    const float* ln1_b = (const float*)d_in[3];
    const float* ln2_g = (const float*)d_in[4];
    const float* ln2_b = (const float*)d_in[5];
    const float* w_qkv = (const float*)d_in[6];
    const float* b_qkv = (const float*)d_in[7];
    const float* w_o   = (const float*)d_in[8];
    const float* b_o   = (const float*)d_in[9];
    const float* w_fc1 = (const float*)d_in[10];
    const float* b_fc1 = (const float*)d_in[11];
    const float* w_fc2 = (const float*)d_in[12];
    const float* b_fc2 = (const float*)d_in[13];
    float* out = (float*)d_out;

    float *x1;
    __nv_bfloat16 *xnh, *xnl, *ath, *atl, *hhp, *hlp, *ach, *acl;
    __nv_bfloat16 *qhp, *qlp, *khp, *klp, *vhp, *vlp;
    __nv_bfloat16 *wqh, *wql, *woh, *wol, *w1h, *w1l, *w2h, *w2l;
    cudaGetSymbolAddress((void**)&x1,   g_x1);
    cudaGetSymbolAddress((void**)&xnh,  g_xn_h);  cudaGetSymbolAddress((void**)&xnl, g_xn_l);
    cudaGetSymbolAddress((void**)&qhp,  g_q_h);   cudaGetSymbolAddress((void**)&qlp, g_q_l);
    cudaGetSymbolAddress((void**)&khp,  g_k_h);   cudaGetSymbolAddress((void**)&klp, g_k_l);
    cudaGetSymbolAddress((void**)&vhp,  g_v_h);   cudaGetSymbolAddress((void**)&vlp, g_v_l);
    cudaGetSymbolAddress((void**)&ath,  g_at_h);  cudaGetSymbolAddress((void**)&atl, g_at_l);
    cudaGetSymbolAddress((void**)&hhp,  g_h_h);   cudaGetSymbolAddress((void**)&hlp, g_h_l);
    cudaGetSymbolAddress((void**)&ach,  g_ac_h);  cudaGetSymbolAddress((void**)&acl, g_ac_l);
    cudaGetSymbolAddress((void**)&wqh,  g_wqkv_h); cudaGetSymbolAddress((void**)&wql, g_wqkv_l);
    cudaGetSymbolAddress((void**)&woh,  g_wo_h);   cudaGetSymbolAddress((void**)&wol, g_wo_l);
    cudaGetSymbolAddress((void**)&w1h,  g_wf1_h);  cudaGetSymbolAddress((void**)&w1l, g_wf1_l);
    cudaGetSymbolAddress((void**)&w2h,  g_wf2_h);  cudaGetSymbolAddress((void**)&w2l, g_wf2_l);

    cudaFuncSetAttribute(attn_tc,
        cudaFuncAttributeMaxDynamicSharedMemorySize, ATT_SMEM);
    cudaFuncSetAttribute(tgemm<1>, cudaFuncAttributeMaxDynamicSharedMemorySize, TG_SMEM);
    cudaFuncSetAttribute(tgemm<2>, cudaFuncAttributeMaxDynamicSharedMemorySize, TG_SMEM);
    cudaFuncSetAttribute(tgemm<3>, cudaFuncAttributeMaxDynamicSharedMemorySize, TG_SMEM);
    cudaFuncSetAttribute(tgemm<4>, cudaFuncAttributeMaxDynamicSharedMemorySize, TG_SMEM);

    const int M = MTOK;

    // weight conversions
    wconv_kernel<<<(3*EMB*EMB)/1024, 256>>>(w_qkv, wqh, wql, 3*EMB*EMB);
    wconv_kernel<<<(EMB*EMB)/1024,   256>>>(w_o,   woh, wol, EMB*EMB);
    wconv_kernel<<<(FF*EMB)/1024,    256>>>(w_fc1, w1h, w1l, FF*EMB);
    wconv_kernel<<<(EMB*FF)/1024,    256>>>(w_fc2, w2h, w2l, EMB*FF);

    // 1) LN1 -> bf16 hi/lo
    ln_kernel<<<M, 256>>>(x, ln1_g, ln1_b, xnh, xnl);

    // 2) QKV GEMM -> head-major q/k/v hi/lo (q pre-scaled)
    {
        dim3 grid(3*EMB/128, M/128);
        tgemm<4><<<grid, 256, TG_SMEM>>>(xnh, xnl, wqh, wql, b_qkv, nullptr,
                                         nullptr, nullptr, nullptr,
                                         qhp, qlp, khp, klp, vhp, vlp,
                                         M, 3*EMB, EMB);
    }

    // 3) tensor-core attention -> at hi/lo
    {
        dim3 grid(SEQ/64, HEADS, BATCH);
        attn_tc<<<grid, 128, ATT_SMEM>>>(qhp, qlp, khp, klp, vhp, vlp, tdp, ath, atl);
    }

    // 4) x1 = attn @ w_o^T + b_o + x   (fp32)
    {
        dim3 grid(EMB/128, M/128);
        tgemm<1><<<grid, 256, TG_SMEM>>>(ath, atl, woh, wol, b_o, x,
                                         x1, nullptr, nullptr,
                                         nullptr, nullptr, nullptr, nullptr, nullptr, nullptr,
                                         M, EMB, EMB);
    }

    // 5) LN2 -> bf16 hi/lo
    ln_kernel<<<M, 256>>>(x1, ln2_g, ln2_b, hhp, hlp);

    // 6) act = gelu(h @ w_fc1^T + b_fc1) -> bf16 hi/lo
    {
        dim3 grid(FF/128, M/128);
        tgemm<2><<<grid, 256, TG_SMEM>>>(hhp, hlp, w1h, w1l, b_fc1, nullptr,
                                         nullptr, ach, acl,
                                         nullptr, nullptr, nullptr, nullptr, nullptr, nullptr,
                                         M, FF, EMB);
    }

    // 7) out = act @ w_fc2^T + b_fc2 + x1
    {
        dim3 grid(EMB/128, M/128);
        tgemm<3><<<grid, 256, TG_SMEM>>>(ach, acl, w2h, w2l, b_fc2, x1,
                                         out, nullptr, nullptr,
                                         nullptr, nullptr, nullptr, nullptr, nullptr, nullptr,
                                         M, EMB, FF);
    }
}

// round 6
// speedup vs baseline: 6.2472x; 1.2474x over previous
#include <cuda_runtime.h>
#include <cuda_bf16.h>
#include <cuda_fp16.h>
#include <math.h>
#include <stdint.h>

// ---------------- Problem constants ----------------
#define BATCH 4
#define SEQ   2048
#define EMB   1024
#define HEADS 16
#define DH    64
#define FF    4096
#define MTOK  (BATCH*SEQ)       // 8192

// ---------------- Scratch ----------------
__device__ __align__(256) float          g_x1  [MTOK * EMB];
__device__ __align__(256) __nv_bfloat16  g_xn_h [MTOK * EMB];
__device__ __align__(256) __nv_bfloat16  g_xn_l [MTOK * EMB];
__device__ __align__(256) __nv_bfloat16  g_q_h  [MTOK * EMB];
__device__ __align__(256) __nv_bfloat16  g_q_l  [MTOK * EMB];
__device__ __align__(256) __nv_bfloat16  g_k_h  [MTOK * EMB];
__device__ __align__(256) __nv_bfloat16  g_k_l  [MTOK * EMB];
__device__ __align__(256) __nv_bfloat16  g_v_h  [MTOK * EMB];
__device__ __align__(256) __nv_bfloat16  g_v_l  [MTOK * EMB];
__device__ __align__(256) __half         g_at_h [MTOK * EMB];
__device__ __align__(256) __half         g_at_l [MTOK * EMB];
__device__ __align__(256) __half         g_h_h  [MTOK * EMB];
__device__ __align__(256) __half         g_h_l  [MTOK * EMB];
__device__ __align__(256) __half         g_ac_h [MTOK * FF];
__device__ __align__(256) __half         g_ac_l [MTOK * FF];
__device__ __align__(256) __nv_bfloat16  g_wqkv_h[3*EMB*EMB];
__device__ __align__(256) __nv_bfloat16  g_wqkv_l[3*EMB*EMB];
__device__ __align__(256) __half         g_wo_f  [EMB*EMB];
__device__ __align__(256) __half         g_wf1_f [FF*EMB];
__device__ __align__(256) __half         g_wf2_f [EMB*FF];

// ================= helpers =================
__device__ __forceinline__ uint32_t smem_u32(const void* p) {
    uint32_t a;
    asm("{ .reg .u64 t; cvta.to.shared.u64 t, %1; cvt.u32.u64 %0, t; }"
        : "=r"(a) : "l"(p));
    return a;
}
#define CP_ASYNC16(dst, src) \
    asm volatile("cp.async.cg.shared.global [%0], [%1], 16;" \
        :: "r"(dst), "l"(src) : "memory")
#define CP_COMMIT() asm volatile("cp.async.commit_group;" ::: "memory")
#define CP_WAIT1()  asm volatile("cp.async.wait_group 1;" ::: "memory")
#define CP_WAIT0()  asm volatile("cp.async.wait_group 0;" ::: "memory")

#define LDSM4(r0,r1,r2,r3, a) \
    asm volatile("ldmatrix.sync.aligned.m8n8.x4.shared.b16 {%0,%1,%2,%3}, [%4];" \
        : "=r"(r0),"=r"(r1),"=r"(r2),"=r"(r3) : "r"(a))
#define LDSM4T(r0,r1,r2,r3, a) \
    asm volatile("ldmatrix.sync.aligned.m8n8.x4.trans.shared.b16 {%0,%1,%2,%3}, [%4];" \
        : "=r"(r0),"=r"(r1),"=r"(r2),"=r"(r3) : "r"(a))

__device__ __forceinline__ void mma16816(float* d, const uint32_t* a, const uint32_t* b) {
    asm volatile(
        "mma.sync.aligned.m16n8k16.row.col.f32.bf16.bf16.f32 "
        "{%0,%1,%2,%3}, {%4,%5,%6,%7}, {%8,%9}, {%0,%1,%2,%3};"
        : "+f"(d[0]),"+f"(d[1]),"+f"(d[2]),"+f"(d[3])
        : "r"(a[0]),"r"(a[1]),"r"(a[2]),"r"(a[3]), "r"(b[0]),"r"(b[1]));
}
__device__ __forceinline__ void mma16816h(float* d, const uint32_t* a, const uint32_t* b) {
    asm volatile(
        "mma.sync.aligned.m16n8k16.row.col.f32.f16.f16.f32 "
        "{%0,%1,%2,%3}, {%4,%5,%6,%7}, {%8,%9}, {%0,%1,%2,%3};"
        : "+f"(d[0]),"+f"(d[1]),"+f"(d[2]),"+f"(d[3])
        : "r"(a[0]),"r"(a[1]),"r"(a[2]),"r"(a[3]), "r"(b[0]),"r"(b[1]));
}

__device__ __forceinline__ float geluf(float x) {
    return 0.5f * x * (1.f + erff(x * 0.70710678118654752f));
}
__device__ __forceinline__ void splito(float v, __nv_bfloat16& h, __nv_bfloat16& l) {
    h = __float2bfloat16_rn(v);
    l = __float2bfloat16_rn(v - __bfloat162float(h));
}
__device__ __forceinline__ void splito(float v, __half& h, __half& l) {
    h = __float2half_rn(v);
    l = __float2half_rn(v - __half2float(h));
}
template<class T>
__device__ __forceinline__ uint32_t packpair(T a, T b) {
    union { T t[2]; uint32_t u; } x; x.t[0] = a; x.t[1] = b; return x.u;
}
__device__ __forceinline__ uint32_t bf2hi(float a, float b) {
    __nv_bfloat162 t = __halves2bfloat162(__float2bfloat16_rn(a), __float2bfloat16_rn(b));
    return *(uint32_t*)&t;
}
__device__ __forceinline__ uint32_t bf2lo(float a, float b, uint32_t hi) {
    float f0 = __uint_as_float(hi << 16);
    float f1 = __uint_as_float(hi & 0xFFFF0000u);
    return bf2hi(a - f0, b - f1);
}

// ============ bf16 3-term GEMM (QKV only): MODE 4 epilogue ============
#define TG_SMEM 131072

template<int MODE>
__global__ void __launch_bounds__(256, 1) tgemm(
    const __nv_bfloat16* __restrict__ Ah, const __nv_bfloat16* __restrict__ Al,
    const __nv_bfloat16* __restrict__ Bh, const __nv_bfloat16* __restrict__ Bl,
    const float* __restrict__ bias,
    __nv_bfloat16* __restrict__ Qh, __nv_bfloat16* __restrict__ Ql,
    __nv_bfloat16* __restrict__ Kh, __nv_bfloat16* __restrict__ Kl,
    __nv_bfloat16* __restrict__ Vh, __nv_bfloat16* __restrict__ Vl,
    int M, int N, int K)
{
    extern __shared__ char smc[];
    const uint32_t smb = smem_u32(smc);
    const int tid = threadIdx.x;
    const int bm = blockIdx.y * 128, bn = blockIdx.x * 128;
    const int nck = K >> 6;
    const int lane = tid & 31, wid = tid >> 5;
    const int wm = wid & 1, wn = wid >> 1;

    float acc[4][4][4];
    #pragma unroll
    for (int i = 0; i < 4; i++)
        #pragma unroll
        for (int j = 0; j < 4; j++)
            #pragma unroll
            for (int e = 0; e < 4; e++) acc[i][j][e] = 0.f;

    const __nv_bfloat16* srcs[4] = {Ah, Al, Bh, Bl};

    auto issue = [&](int stage, int ck) {
        uint32_t sbase = smb + stage * 65536;
        #pragma unroll
        for (int t4 = 0; t4 < 4; t4++) {
            const __nv_bfloat16* s = srcs[t4];
            const int rbase = (t4 < 2) ? bm : bn;
            #pragma unroll
            for (int p = 0; p < 4; p++) {
                int cid = tid + p * 256;
                int row = cid >> 3, c = cid & 7;
                const void* g = s + (size_t)(rbase + row) * K + ck * 64 + c * 8;
                uint32_t d = sbase + t4 * 16384 + row * 128 + ((c ^ (row & 7)) * 16);
                CP_ASYNC16(d, g);
            }
        }
        CP_COMMIT();
    };

    const int arl = (lane & 7) + ((lane >> 3) & 1) * 8;
    const int acf = lane >> 4;
    const int brl = (lane & 7) + ((lane >> 4) & 1) * 8;
    const int bcf = (lane >> 3) & 1;

    auto domma = [&](int stage) {
        uint32_t Ab  = smb + stage * 65536;
        uint32_t Alb = Ab + 16384;
        uint32_t Bb  = Ab + 32768;
        uint32_t Blb = Ab + 49152;
        #pragma unroll
        for (int k16 = 0; k16 < 4; k16++) {
            uint32_t ah[4][4], al[4][4];
            #pragma unroll
            for (int mi = 0; mi < 4; mi++) {
                int r = wm * 64 + mi * 16 + arl;
                int c = k16 * 2 + acf;
                uint32_t off = r * 128 + ((c ^ (r & 7)) * 16);
                LDSM4(ah[mi][0], ah[mi][1], ah[mi][2], ah[mi][3], Ab  + off);
                LDSM4(al[mi][0], al[mi][1], al[mi][2], al[mi][3], Alb + off);
            }
            uint32_t bh[2][4], bl[2][4];
            #pragma unroll
            for (int np = 0; np < 2; np++) {
                int r = wn * 32 + np * 16 + brl;
                int c = k16 * 2 + bcf;
                uint32_t off = r * 128 + ((c ^ (r & 7)) * 16);
                LDSM4(bh[np][0], bh[np][1], bh[np][2], bh[np][3], Bb  + off);
                LDSM4(bl[np][0], bl[np][1], bl[np][2], bl[np][3], Blb + off);
            }
            #pragma unroll
            for (int mi = 0; mi < 4; mi++)
                #pragma unroll
                for (int ni = 0; ni < 4; ni++) {
                    const uint32_t* bph = &bh[ni >> 1][(ni & 1) * 2];
                    const uint32_t* bpl = &bl[ni >> 1][(ni & 1) * 2];
                    mma16816(acc[mi][ni], ah[mi], bph);
                    mma16816(acc[mi][ni], al[mi], bph);
                    mma16816(acc[mi][ni], ah[mi], bpl);
                }
        }
    };

    issue(0, 0);
    if (nck > 1) issue(1, 1);
    for (int ck = 0; ck < nck; ck++) {
        if (ck + 1 < nck) { CP_WAIT1(); } else { CP_WAIT0(); }
        __syncthreads();
        domma(ck & 1);
        __syncthreads();
        if (ck + 2 < nck) issue(ck & 1, ck + 2);
    }

    const int r_l = lane >> 2, c_l = (lane & 3) * 2;
    #pragma unroll
    for (int mi = 0; mi < 4; mi++) {
        #pragma unroll
        for (int ni = 0; ni < 4; ni++) {
            const int col = bn + wn * 32 + ni * 8 + c_l;
            const float2 bv = *(const float2*)(bias + col);
            #pragma unroll
            for (int h2 = 0; h2 < 2; h2++) {
                const int row = bm + wm * 64 + mi * 16 + r_l + h2 * 8;
                float v0 = acc[mi][ni][h2*2+0] + bv.x;
                float v1 = acc[mi][ni][h2*2+1] + bv.y;
                // MODE 4: scatter to head-major q/k/v hi/lo (q scaled)
                int sec = col >> 10;
                int hd  = (col & 1023) >> 6;
                int dch = col & 63;
                int bb = row >> 11, s = row & 2047;
                size_t di = (((size_t)bb * HEADS + hd) * SEQ + s) * DH + dch;
                float sc = (sec == 0) ? 0.125f : 1.f;
                v0 *= sc; v1 *= sc;
                __nv_bfloat16 h0, l0, h1, l1;
                splito(v0, h0, l0); splito(v1, h1, l1);
                __nv_bfloat16* dsth = (sec == 0) ? Qh : (sec == 1) ? Kh : Vh;
                __nv_bfloat16* dstl = (sec == 0) ? Ql : (sec == 1) ? Kl : Vl;
                *(uint32_t*)(dsth + di) = packpair(h0, h1);
                *(uint32_t*)(dstl + di) = packpair(l0, l1);
            }
        }
    }
}

// ============ fp16 2-term GEMM (A hi/lo fp16, B single fp16) ============
// MODE 1: fp32 +bias+res   MODE 2: gelu(+bias)->fp16 hi/lo   MODE 3: = 1
#define TG2_STAGE 49152
#define TG2_SMEM (2*TG2_STAGE)   // 98304

template<int MODE>
__global__ void __launch_bounds__(256, 1) tgemm_h(
    const __half* __restrict__ Ah, const __half* __restrict__ Al,
    const __half* __restrict__ Bs,
    const float* __restrict__ bias, const float* __restrict__ res,
    float* __restrict__ C, __half* __restrict__ Ch, __half* __restrict__ Cl,
    int M, int N, int K)
{
    extern __shared__ char smc[];
    const uint32_t smb = smem_u32(smc);
    const int tid = threadIdx.x;
    const int bm = blockIdx.y * 128, bn = blockIdx.x * 128;
    const int nck = K >> 6;
    const int lane = tid & 31, wid = tid >> 5;
    const int wm = wid & 1, wn = wid >> 1;

    float acc[4][4][4];
    #pragma unroll
    for (int i = 0; i < 4; i++)
        #pragma unroll
        for (int j = 0; j < 4; j++)
            #pragma unroll
            for (int e = 0; e < 4; e++) acc[i][j][e] = 0.f;

    const __half* srcs[3] = {Ah, Al, Bs};

    auto issue = [&](int stage, int ck) {
        uint32_t sbase = smb + stage * TG2_STAGE;
        #pragma unroll
        for (int t4 = 0; t4 < 3; t4++) {
            const __half* s = srcs[t4];
            const int rbase = (t4 < 2) ? bm : bn;
            #pragma unroll
            for (int p = 0; p < 4; p++) {
                int cid = tid + p * 256;
                int row = cid >> 3, c = cid & 7;
                const void* g = s + (size_t)(rbase + row) * K + ck * 64 + c * 8;
                uint32_t d = sbase + t4 * 16384 + row * 128 + ((c ^ (row & 7)) * 16);
                CP_ASYNC16(d, g);
            }
        }
        CP_COMMIT();
    };

    const int arl = (lane & 7) + ((lane >> 3) & 1) * 8;
    const int acf = lane >> 4;
    const int brl = (lane & 7) + ((lane >> 4) & 1) * 8;
    const int bcf = (lane >> 3) & 1;

    auto domma = [&](int stage) {
        uint32_t Ab  = smb + stage * TG2_STAGE;
        uint32_t Alb = Ab + 16384;
        uint32_t Bb  = Ab + 32768;
        #pragma unroll
        for (int k16 = 0; k16 < 4; k16++) {
            uint32_t ah[4][4], al[4][4];
            #pragma unroll
            for (int mi = 0; mi < 4; mi++) {
                int r = wm * 64 + mi * 16 + arl;
                int c = k16 * 2 + acf;
                uint32_t off = r * 128 + ((c ^ (r & 7)) * 16);
                LDSM4(ah[mi][0], ah[mi][1], ah[mi][2], ah[mi][3], Ab  + off);
                LDSM4(al[mi][0], al[mi][1], al[mi][2], al[mi][3], Alb + off);
            }
            uint32_t bh[2][4];
            #pragma unroll
            for (int np = 0; np < 2; np++) {
                int r = wn * 32 + np * 16 + brl;
                int c = k16 * 2 + bcf;
                uint32_t off = r * 128 + ((c ^ (r & 7)) * 16);
                LDSM4(bh[np][0], bh[np][1], bh[np][2], bh[np][3], Bb + off);
            }
            #pragma unroll
            for (int mi = 0; mi < 4; mi++)
                #pragma unroll
                for (int ni = 0; ni < 4; ni++) {
                    const uint32_t* bph = &bh[ni >> 1][(ni & 1) * 2];
                    mma16816h(acc[mi][ni], ah[mi], bph);
                    mma16816h(acc[mi][ni], al[mi], bph);
                }
        }
    };

    issue(0, 0);
    if (nck > 1) issue(1, 1);
    for (int ck = 0; ck < nck; ck++) {
        if (ck + 1 < nck) { CP_WAIT1(); } else { CP_WAIT0(); }
        __syncthreads();
        domma(ck & 1);
        __syncthreads();
        if (ck + 2 < nck) issue(ck & 1, ck + 2);
    }

    const int r_l = lane >> 2, c_l = (lane & 3) * 2;
    #pragma unroll
    for (int mi = 0; mi < 4; mi++) {
        #pragma unroll
        for (int ni = 0; ni < 4; ni++) {
            const int col = bn + wn * 32 + ni * 8 + c_l;
            const float2 bv = *(const float2*)(bias + col);
            #pragma unroll
            for (int h2 = 0; h2 < 2; h2++) {
                const int row = bm + wm * 64 + mi * 16 + r_l + h2 * 8;
                float v0 = acc[mi][ni][h2*2+0] + bv.x;
                float v1 = acc[mi][ni][h2*2+1] + bv.y;
                if (MODE == 1 || MODE == 3) {
                    float2 rr = *(const float2*)(res + (size_t)row * N + col);
                    v0 += rr.x; v1 += rr.y;
                    *(float2*)(C + (size_t)row * N + col) = make_float2(v0, v1);
                } else {  // MODE 2
                    v0 = geluf(v0); v1 = geluf(v1);
                    __half h0, l0, h1, l1;
                    splito(v0, h0, l0); splito(v1, h1, l1);
                    *(uint32_t*)(Ch + (size_t)row * N + col) = packpair(h0, h1);
                    *(uint32_t*)(Cl + (size_t)row * N + col) = packpair(l0, l1);
                }
            }
        }
    }
}

// ---------------- weight conversions ----------------
__global__ void __launch_bounds__(256) wconv_kernel(
    const float* __restrict__ s, __nv_bfloat16* __restrict__ h,
    __nv_bfloat16* __restrict__ l, int n)
{
    int i = (blockIdx.x * 256 + threadIdx.x) * 4;
    if (i >= n) return;
    float4 v = *(const float4*)(s + i);
    __nv_bfloat16 h0,l0,h1,l1,h2,l2,h3,l3;
    splito(v.x,h0,l0); splito(v.y,h1,l1); splito(v.z,h2,l2); splito(v.w,h3,l3);
    *(uint32_t*)(h + i)     = packpair(h0, h1);
    *(uint32_t*)(h + i + 2) = packpair(h2, h3);
    *(uint32_t*)(l + i)     = packpair(l0, l1);
    *(uint32_t*)(l + i + 2) = packpair(l2, l3);
}
__global__ void __launch_bounds__(256) wconv_h(
    const float* __restrict__ s, __half* __restrict__ o, int n)
{
    int i = (blockIdx.x * 256 + threadIdx.x) * 4;
    if (i >= n) return;
    float4 v = *(const float4*)(s + i);
    *(uint32_t*)(o + i)     = packpair(__float2half_rn(v.x), __float2half_rn(v.y));
    *(uint32_t*)(o + i + 2) = packpair(__float2half_rn(v.z), __float2half_rn(v.w));
}

// ---------------- LayerNorm -> hi/lo (bf16 or fp16) ----------------
template<class T>
__global__ void __launch_bounds__(256) ln_kernel(const float* __restrict__ x,
                                                 const float* __restrict__ gam,
                                                 const float* __restrict__ bet,
                                                 T* __restrict__ oh,
                                                 T* __restrict__ ol)
{
    int row = blockIdx.x;
    const float4* xr = (const float4*)(x + (size_t)row * EMB);
    float4 v = xr[threadIdx.x];
    float s  = v.x + v.y + v.z + v.w;
    float ss = v.x*v.x + v.y*v.y + v.z*v.z + v.w*v.w;
    #pragma unroll
    for (int o = 16; o; o >>= 1) {
        s  += __shfl_xor_sync(0xffffffffu, s,  o);
        ss += __shfl_xor_sync(0xffffffffu, ss, o);
    }
    __shared__ float sh[2][8];
    int w = threadIdx.x >> 5, l = threadIdx.x & 31;
    if (l == 0) { sh[0][w] = s; sh[1][w] = ss; }
    __syncthreads();
    if (threadIdx.x < 32) {
        float a  = (l < 8) ? sh[0][l] : 0.f;
        float bb = (l < 8) ? sh[1][l] : 0.f;
        #pragma unroll
        for (int o = 4; o; o >>= 1) {
            a  += __shfl_xor_sync(0xffffffffu, a,  o);
            bb += __shfl_xor_sync(0xffffffffu, bb, o);
        }
        if (l == 0) { sh[0][0] = a; sh[1][0] = bb; }
    }
    __syncthreads();
    float mean = sh[0][0] * (1.f / EMB);
    float var  = sh[1][0] * (1.f / EMB) - mean * mean;
    float inv  = rsqrtf(var + 1e-5f);
    int c = threadIdx.x * 4;
    float4 gg  = *(const float4*)(gam + c);
    float4 bb4 = *(const float4*)(bet + c);
    float o0 = (v.x - mean) * inv * gg.x + bb4.x;
    float o1 = (v.y - mean) * inv * gg.y + bb4.y;
    float o2 = (v.z - mean) * inv * gg.z + bb4.z;
    float o3 = (v.w - mean) * inv * gg.w + bb4.w;
    T h0,l0,h1,l1,h2,l2,h3,l3;
    splito(o0,h0,l0); splito(o1,h1,l1); splito(o2,h2,l2); splito(o3,h3,l3);
    size_t base = (size_t)row * EMB + c;
    *(uint32_t*)(oh + base)     = packpair(h0, h1);
    *(uint32_t*)(oh + base + 2) = packpair(h2, h3);
    *(uint32_t*)(ol + base)     = packpair(l0, l1);
    *(uint32_t*)(ol + base + 2) = packpair(l2, l3);
}

// ---------------- Tensor-core flash attention ----------------
#define ATT_SMEM (16384 + 2*32768)

__global__ void __launch_bounds__(128, 1) attn_tc(
    const __nv_bfloat16* __restrict__ qh, const __nv_bfloat16* __restrict__ ql,
    const __nv_bfloat16* __restrict__ kh, const __nv_bfloat16* __restrict__ kl,
    const __nv_bfloat16* __restrict__ vh, const __nv_bfloat16* __restrict__ vl,
    const int* __restrict__ tdp,
    __half* __restrict__ oh, __half* __restrict__ ol)
{
    extern __shared__ char smc[];
    const uint32_t smb = smem_u32(smc);
    const int qt = (SEQ/64 - 1) - blockIdx.x;   // longest first
    const int h = blockIdx.y, b = blockIdx.z;
    const int tid = threadIdx.x, lane = tid & 31, wid = tid >> 5;
    const int td = *tdp;

    const size_t hb = ((size_t)b * HEADS + h) * SEQ * DH;
    const __nv_bfloat16* srcs[4] = {kh + hb, kl + hb, vh + hb, vl + hb};
    const int nkt = qt + 1;

    auto issue = [&](int stage, int kt) {
        uint32_t sb = smb + 16384 + stage * 32768;
        #pragma unroll
        for (int t4 = 0; t4 < 4; t4++) {
            #pragma unroll
            for (int p = 0; p < 4; p++) {
                int cid = tid + p * 128;
                int row = cid >> 3, c = cid & 7;
                const void* g = srcs[t4] + (size_t)(kt * 64 + row) * DH + c * 8;
                uint32_t d = sb + t4 * 8192 + row * 128 + ((c ^ (row & 7)) * 16);
                CP_ASYNC16(d, g);
            }
        }
        CP_COMMIT();
    };

    issue(0, 0);
    if (nkt > 1) issue(1, 1);

    // Q tile -> smem
    {
        const __nv_bfloat16* qhp = qh + hb;
        const __nv_bfloat16* qlp = ql + hb;
        #pragma unroll
        for (int p = 0; p < 4; p++) {
            int cid = tid + p * 128;
            int row = cid >> 3, c = cid & 7;
            uint32_t sw = row * 128 + ((c ^ (row & 7)) * 16);
            size_t g = (size_t)(qt * 64 + row) * DH + c * 8;
            *(uint4*)(smc + sw)        = *(const uint4*)(qhp + g);
            *(uint4*)(smc + 8192 + sw) = *(const uint4*)(qlp + g);
        }
    }
    __syncthreads();

    const int arl = (lane & 7) + ((lane >> 3) & 1) * 8;
    const int acf = lane >> 4;
    uint32_t qfh[4][4], qfl[4][4];
    #pragma unroll
    for (int j = 0; j < 4; j++) {
        int r = wid * 16 + arl;
        int c = j * 2 + acf;
        uint32_t off = r * 128 + ((c ^ (r & 7)) * 16);
        LDSM4(qfh[j][0], qfh[j][1], qfh[j][2], qfh[j][3], smb + off);
        LDSM4(qfl[j][0], qfl[j][1], qfl[j][2], qfl[j][3], smb + 8192 + off);
    }

    const int r_l = lane >> 2, c_l = lane & 3;
    const int brl = (lane & 7) + ((lane >> 4) & 1) * 8;
    const int bcf = (lane >> 3) & 1;
    const int vr  = (lane & 7) + ((lane >> 3) & 1) * 8;
    const int vc  = lane >> 4;

    // ---- precompute periodic mask (fast path when 64 % td == 0) ----
    const bool tdper = (64 % td) == 0;
    uint32_t pmask_s = 0;
    if (tdper) {
        #pragma unroll
        for (int t = 0; t < 8; t++)
            for (int e1 = 0; e1 < 2; e1++) {
                int off = t * 8 + c_l * 2 + e1;
                if ((off % td) == td - 1) pmask_s |= 1u << (t * 2 + e1);
            }
    }

    float O[8][4] = {};
    float mrun[2] = {-1e30f, -1e30f}, lrun[2] = {0.f, 0.f};
    const int grow = qt * 64 + wid * 16 + r_l;

    for (int kt = 0; kt < nkt; kt++) {
        if (kt + 1 < nkt) { CP_WAIT1(); } else { CP_WAIT0(); }
        __syncthreads();
        uint32_t sb  = smb + 16384 + (kt & 1) * 32768;
        uint32_t KHb = sb, KLb = sb + 8192, VHb = sb + 16384, VLb = sb + 24576;

        // ---- scores ----
        float sacc[8][4];
        #pragma unroll
        for (int t = 0; t < 8; t++)
            #pragma unroll
            for (int e = 0; e < 4; e++) sacc[t][e] = 0.f;

        #pragma unroll
        for (int j = 0; j < 4; j++) {
            uint32_t bhf[4][4], blf[4][4];
            #pragma unroll
            for (int np = 0; np < 4; np++) {
                int r = np * 16 + brl;
                int c = j * 2 + bcf;
                uint32_t off = r * 128 + ((c ^ (r & 7)) * 16);
                LDSM4(bhf[np][0], bhf[np][1], bhf[np][2], bhf[np][3], KHb + off);
                LDSM4(blf[np][0], blf[np][1], blf[np][2], blf[np][3], KLb + off);
            }
            #pragma unroll
            for (int np = 0; np < 4; np++) {
                mma16816(sacc[2*np],   qfh[j], &bhf[np][0]);
                mma16816(sacc[2*np],   qfl[j], &bhf[np][0]);
                mma16816(sacc[2*np],   qfh[j], &blf[np][0]);
                mma16816(sacc[2*np+1], qfh[j], &bhf[np][2]);
                mma16816(sacc[2*np+1], qfl[j], &bhf[np][2]);
                mma16816(sacc[2*np+1], qfh[j], &blf[np][2]);
            }
        }

        // ---- mask: periodic via precomputed bits; causal only on diagonal ----
        uint32_t pm = pmask_s;
        if (!tdper) {
            pm = 0;
            for (int i = 0; i < 16; i++) {
                int t = i >> 1, e1 = i & 1;
                int gk = kt * 64 + t * 8 + c_l * 2 + e1;
                if ((gk % td) == td - 1) pm |= 1u << i;
            }
        }
        if (kt == qt) {
            #pragma unroll
            for (int t = 0; t < 8; t++)
                #pragma unroll
                for (int e = 0; e < 4; e++) {
                    int gk = kt * 64 + t * 8 + c_l * 2 + (e & 1);
                    int gq = grow + (e >> 1) * 8;
                    if (((pm >> (t * 2 + (e & 1))) & 1) || gk > gq)
                        sacc[t][e] = -1e30f;
                }
        } else {
            #pragma unroll
            for (int t = 0; t < 8; t++)
                #pragma unroll
                for (int e = 0; e < 4; e++) {
                    if ((pm >> (t * 2 + (e & 1))) & 1)
                        sacc[t][e] = -1e30f;
                }
        }

        // ---- online softmax ----
        #pragma unroll
        for (int rh = 0; rh < 2; rh++) {
            float mx = -1e30f;
            #pragma unroll
            for (int t = 0; t < 8; t++) {
                mx = fmaxf(mx, sacc[t][rh*2]);
                mx = fmaxf(mx, sacc[t][rh*2+1]);
            }
            mx = fmaxf(mx, __shfl_xor_sync(0xffffffffu, mx, 1));
            mx = fmaxf(mx, __shfl_xor_sync(0xffffffffu, mx, 2));
            float mnew  = fmaxf(mrun[rh], mx);
            float alpha = __expf(mrun[rh] - mnew);
            float sum = 0.f;
            #pragma unroll
            for (int t = 0; t < 8; t++) {
                float p0 = __expf(sacc[t][rh*2]   - mnew);
                float p1 = __expf(sacc[t][rh*2+1] - mnew);
                sacc[t][rh*2] = p0; sacc[t][rh*2+1] = p1;
                sum += p0 + p1;
            }
            sum += __shfl_xor_sync(0xffffffffu, sum, 1);
            sum += __shfl_xor_sync(0xffffffffu, sum, 2);
            lrun[rh] = lrun[rh] * alpha + sum;
            mrun[rh] = mnew;
            #pragma unroll
            for (int d = 0; d < 8; d++) {
                O[d][rh*2]   *= alpha;
                O[d][rh*2+1] *= alpha;
            }
        }

        // ---- O += P V ----
        #pragma unroll
        for (int j = 0; j < 4; j++) {
            uint32_t pah[4], pal[4];
            pah[0] = bf2hi(sacc[2*j][0],   sacc[2*j][1]);
            pah[1] = bf2hi(sacc[2*j][2],   sacc[2*j][3]);
            pah[2] = bf2hi(sacc[2*j+1][0], sacc[2*j+1][1]);
            pah[3] = bf2hi(sacc[2*j+1][2], sacc[2*j+1][3]);
            pal[0] = bf2lo(sacc[2*j][0],   sacc[2*j][1],   pah[0]);
            pal[1] = bf2lo(sacc[2*j][2],   sacc[2*j][3],   pah[1]);
            pal[2] = bf2lo(sacc[2*j+1][0], sacc[2*j+1][1], pah[2]);
            pal[3] = bf2lo(sacc[2*j+1][2], sacc[2*j+1][3], pah[3]);
            #pragma unroll
            for (int dp = 0; dp < 4; dp++) {
                uint32_t bvh[4], bvl[4];
                int r = j * 16 + vr;
                int c = dp * 2 + vc;
                uint32_t off = r * 128 + ((c ^ (r & 7)) * 16);
                LDSM4T(bvh[0], bvh[1], bvh[2], bvh[3], VHb + off);
                LDSM4T(bvl[0], bvl[1], bvl[2], bvl[3], VLb + off);
                mma16816(O[2*dp],   pah, &bvh[0]);
                mma16816(O[2*dp],   pal, &bvh[0]);
                mma16816(O[2*dp],   pah, &bvl[0]);
                mma16816(O[2*dp+1], pah, &bvh[2]);
                mma16816(O[2*dp+1], pal, &bvh[2]);
                mma16816(O[2*dp+1], pah, &bvl[2]);
            }
        }

        __syncthreads();
        if (kt + 2 < nkt) issue(kt & 1, kt + 2);
    }

    // ---- write O (token-major fp16 hi/lo) ----
    #pragma unroll
    for (int rh = 0; rh < 2; rh++) {
        float inv = 1.f / lrun[rh];
        int tok = b * SEQ + qt * 64 + wid * 16 + r_l + rh * 8;
        size_t base = (size_t)tok * EMB + h * DH + c_l * 2;
        #pragma unroll
        for (int t = 0; t < 8; t++) {
            float v0 = O[t][rh*2]   * inv;
            float v1 = O[t][rh*2+1] * inv;
            __half h0, l0, h1, l1;
            splito(v0, h0, l0); splito(v1, h1, l1);
            *(uint32_t*)(oh + base + t*8) = packpair(h0, h1);
            *(uint32_t*)(ol + base + t*8) = packpair(l0, l1);
        }
    }
}

// ---------------- Launch ----------------
extern "C" void kernel_launch(void* const* d_in, const int* in_sizes, int n_in,
                              void* d_out, int out_size)
{
    const float* x     = (const float*)d_in[0];
    const int*   tdp   = (const int*)  d_in[1];
    const float* ln1_g = (const float*)d_in[2];
    const float* ln1_b = (const float*)d_in[3];
    const float* ln2_g = (const float*)d_in[4];
    const float* ln2_b = (const float*)d_in[5];
    const float* w_qkv = (const float*)d_in[6];
    const float* b_qkv = (const float*)d_in[7];
    const float* w_o   = (const float*)d_in[8];
    const float* b_o   = (const float*)d_in[9];
    const float* w_fc1 = (const float*)d_in[10];
    const float* b_fc1 = (const float*)d_in[11];
    const float* w_fc2 = (const float*)d_in[12];
    const float* b_fc2 = (const float*)d_in[13];
    float* out = (float*)d_out;

    float *x1;
    __nv_bfloat16 *xnh, *xnl, *qhp, *qlp, *khp, *klp, *vhp, *vlp, *wqh, *wql;
    __half *ath, *atl, *hhp, *hlp, *ach, *acl, *wof, *w1f, *w2f;
    cudaGetSymbolAddress((void**)&x1,   g_x1);
    cudaGetSymbolAddress((void**)&xnh,  g_xn_h);  cudaGetSymbolAddress((void**)&xnl, g_xn_l);
    cudaGetSymbolAddress((void**)&qhp,  g_q_h);   cudaGetSymbolAddress((void**)&qlp, g_q_l);
    cudaGetSymbolAddress((void**)&khp,  g_k_h);   cudaGetSymbolAddress((void**)&klp, g_k_l);
    cudaGetSymbolAddress((void**)&vhp,  g_v_h);   cudaGetSymbolAddress((void**)&vlp, g_v_l);
    cudaGetSymbolAddress((void**)&ath,  g_at_h);  cudaGetSymbolAddress((void**)&atl, g_at_l);
    cudaGetSymbolAddress((void**)&hhp,  g_h_h);   cudaGetSymbolAddress((void**)&hlp, g_h_l);
    cudaGetSymbolAddress((void**)&ach,  g_ac_h);  cudaGetSymbolAddress((void**)&acl, g_ac_l);
    cudaGetSymbolAddress((void**)&wqh,  g_wqkv_h); cudaGetSymbolAddress((void**)&wql, g_wqkv_l);
    cudaGetSymbolAddress((void**)&wof,  g_wo_f);
    cudaGetSymbolAddress((void**)&w1f,  g_wf1_f);
    cudaGetSymbolAddress((void**)&w2f,  g_wf2_f);

    cudaFuncSetAttribute(attn_tc,
        cudaFuncAttributeMaxDynamicSharedMemorySize, ATT_SMEM);
    cudaFuncSetAttribute(tgemm<4>,   cudaFuncAttributeMaxDynamicSharedMemorySize, TG_SMEM);
    cudaFuncSetAttribute(tgemm_h<1>, cudaFuncAttributeMaxDynamicSharedMemorySize, TG2_SMEM);
    cudaFuncSetAttribute(tgemm_h<2>, cudaFuncAttributeMaxDynamicSharedMemorySize, TG2_SMEM);
    cudaFuncSetAttribute(tgemm_h<3>, cudaFuncAttributeMaxDynamicSharedMemorySize, TG2_SMEM);

    const int M = MTOK;

    // weight conversions
    wconv_kernel<<<(3*EMB*EMB)/1024, 256>>>(w_qkv, wqh, wql, 3*EMB*EMB);
    wconv_h<<<(EMB*EMB)/1024, 256>>>(w_o,   wof, EMB*EMB);
    wconv_h<<<(FF*EMB)/1024,  256>>>(w_fc1, w1f, FF*EMB);
    wconv_h<<<(EMB*FF)/1024,  256>>>(w_fc2, w2f, EMB*FF);

    // 1) LN1 -> bf16 hi/lo
    ln_kernel<__nv_bfloat16><<<M, 256>>>(x, ln1_g, ln1_b, xnh, xnl);

    // 2) QKV GEMM (bf16 3-term) -> head-major q/k/v bf16 hi/lo
    {
        dim3 grid(3*EMB/128, M/128);
        tgemm<4><<<grid, 256, TG_SMEM>>>(xnh, xnl, wqh, wql, b_qkv,
                                         qhp, qlp, khp, klp, vhp, vlp,
                                         M, 3*EMB, EMB);
    }

    // 3) attention -> fp16 hi/lo
    {
        dim3 grid(SEQ/64, HEADS, BATCH);
        attn_tc<<<grid, 128, ATT_SMEM>>>(qhp, qlp, khp, klp, vhp, vlp, tdp, ath, atl);
    }

    // 4) x1 = attn @ w_o^T + b_o + x   (fp16 2-term)
    {
        dim3 grid(EMB/128, M/128);
        tgemm_h<1><<<grid, 256, TG2_SMEM>>>(ath, atl, wof, b_o, x,
                                            x1, nullptr, nullptr, M, EMB, EMB);
    }

    // 5) LN2 -> fp16 hi/lo
    ln_kernel<__half><<<M, 256>>>(x1, ln2_g, ln2_b, hhp, hlp);

    // 6) act = gelu(h @ w_fc1^T + b_fc1) -> fp16 hi/lo
    {
        dim3 grid(FF/128, M/128);
        tgemm_h<2><<<grid, 256, TG2_SMEM>>>(hhp, hlp, w1f, b_fc1, nullptr,
                                            nullptr, ach, acl, M, FF, EMB);
    }

    // 7) out = act @ w_fc2^T + b_fc2 + x1
    {
        dim3 grid(EMB/128, M/128);
        tgemm_h<3><<<grid, 256, TG2_SMEM>>>(ach, acl, w2f, b_fc2, x1,
                                            out, nullptr, nullptr, M, EMB, FF);
    }
}